// round 7
// baseline (speedup 1.0000x reference)
#include <cuda_runtime.h>
#include <math.h>

// Problem shapes (fixed by reference)
#define Bsz   64
#define Ssz   512
#define Esz   768
#define Hsz   768
#define Csz   9
#define NTOK  (Bsz * Ssz)          // 32768 tokens
#define IGNORE_LBL (-100)
#define TAU_F  0.7f
#define QGCE_F 0.7f

// Scratch: h = tanh(hidden @ W1 + b1), [NTOK, H] fp32 (96 MB, static device mem)
__device__ float g_h[(size_t)NTOK * Hsz];
// Fallback probs sink (only used if out_size doesn't include probs)
__device__ float g_probs_sink[(size_t)NTOK * Csz];
// Deterministic loss partials (one per block of kernel 2)
#define LOSS_BLOCKS 256
__device__ float g_partials[LOSS_BLOCKS];

// ---------------------------------------------------------------------------
// Kernel 1: h = tanh(hidden @ W1 + b1)
// A: [NTOK, E] row-major, B(W1): [E, H] row-major, Out: [NTOK, H]
// Tiling: BM=128, BN=128, BK=8, 256 threads, 8x8 outputs/thread.
// Software-pipelined: tile kt+1 is prefetched into registers while tile kt
// is being computed from shared memory, hiding the ~250-cycle L2 latency
// behind the 512 FFMAs of the compute phase.
// All dims divide exactly (32768/128, 768/128, 768/8) -> no boundary code.
// ---------------------------------------------------------------------------
__global__ __launch_bounds__(256, 2)
void gemm1_tanh_kernel(const float* __restrict__ A,
                       const float* __restrict__ B,
                       const float* __restrict__ bias,
                       float* __restrict__ Out)
{
    const int BM = 128, BN = 128, BK = 8;
    __shared__ float As[BK][BM];   // transposed A tile: As[k][m]
    __shared__ float Bs[BK][BN];   // Bs[k][n]

    const int tid      = threadIdx.x;
    const int blockRow = blockIdx.y;   // 0..255 (M tiles)
    const int blockCol = blockIdx.x;   // 0..5   (N tiles)

    const float* Ablk = A + (size_t)blockRow * BM * Esz;
    const float* Bblk = B + (size_t)blockCol * BN;

    // Global->shared load mapping (one float4 per thread per tile)
    const int aRow  = tid >> 1;            // 0..127
    const int aCol4 = (tid & 1) * 4;       // 0 or 4
    const int bRow  = tid >> 5;            // 0..7
    const int bCol4 = (tid & 31) * 4;      // 0..124

    // Compute mapping: 16x16 thread grid, 8x8 micro-tile
    const int trow = (tid >> 4) * 8;       // row base in tile
    const int tcol = (tid & 15) * 8;       // col base in tile

    float acc[8][8];
#pragma unroll
    for (int i = 0; i < 8; i++)
#pragma unroll
        for (int j = 0; j < 8; j++) acc[i][j] = 0.0f;

    const float* aPtr = Ablk + (size_t)aRow * Esz + aCol4;          // +kt*BK each tile
    const float* bPtr = Bblk + (size_t)bRow * Hsz + bCol4;          // +kt*BK*Hsz each tile

    // Prologue: load tile 0 into registers, stage to smem
    float4 av = *reinterpret_cast<const float4*>(aPtr);
    float4 bv = *reinterpret_cast<const float4*>(bPtr);

    const int NK = Esz / BK;   // 96
    for (int kt = 0; kt < NK; ++kt) {
        // Stage current tile's registers into shared memory
        As[aCol4 + 0][aRow] = av.x;
        As[aCol4 + 1][aRow] = av.y;
        As[aCol4 + 2][aRow] = av.z;
        As[aCol4 + 3][aRow] = av.w;
        *reinterpret_cast<float4*>(&Bs[bRow][bCol4]) = bv;
        __syncthreads();

        // Prefetch next tile into registers (overlaps with compute below)
        if (kt + 1 < NK) {
            av = *reinterpret_cast<const float4*>(aPtr + (kt + 1) * BK);
            bv = *reinterpret_cast<const float4*>(bPtr + (size_t)(kt + 1) * BK * Hsz);
        }

#pragma unroll
        for (int k = 0; k < BK; ++k) {
            float ra[8], rb[8];
            *reinterpret_cast<float4*>(&ra[0]) =
                *reinterpret_cast<const float4*>(&As[k][trow]);
            *reinterpret_cast<float4*>(&ra[4]) =
                *reinterpret_cast<const float4*>(&As[k][trow + 4]);
            *reinterpret_cast<float4*>(&rb[0]) =
                *reinterpret_cast<const float4*>(&Bs[k][tcol]);
            *reinterpret_cast<float4*>(&rb[4]) =
                *reinterpret_cast<const float4*>(&Bs[k][tcol + 4]);
#pragma unroll
            for (int i = 0; i < 8; i++)
#pragma unroll
                for (int j = 0; j < 8; j++)
                    acc[i][j] += ra[i] * rb[j];
        }
        __syncthreads();
    }

    // Epilogue: bias + tanh, store to scratch
    const int rowbase = blockRow * BM + trow;
    const int colbase = blockCol * BN + tcol;
    float bvals[8];
#pragma unroll
    for (int j = 0; j < 8; j++) bvals[j] = bias[colbase + j];

#pragma unroll
    for (int i = 0; i < 8; i++) {
        float4 o0, o1;
        o0.x = tanhf(acc[i][0] + bvals[0]);
        o0.y = tanhf(acc[i][1] + bvals[1]);
        o0.z = tanhf(acc[i][2] + bvals[2]);
        o0.w = tanhf(acc[i][3] + bvals[3]);
        o1.x = tanhf(acc[i][4] + bvals[4]);
        o1.y = tanhf(acc[i][5] + bvals[5]);
        o1.z = tanhf(acc[i][6] + bvals[6]);
        o1.w = tanhf(acc[i][7] + bvals[7]);
        float* orow = Out + (size_t)(rowbase + i) * Hsz + colbase;
        *reinterpret_cast<float4*>(orow)     = o0;
        *reinterpret_cast<float4*>(orow + 4) = o1;
    }
}

// ---------------------------------------------------------------------------
// Kernel 2: logits = h @ W2 + b2; softmax over C=9; write probs; per-block
// deterministic loss partials. One warp per token.
// ---------------------------------------------------------------------------
__global__ __launch_bounds__(256)
void head_softmax_loss_kernel(const float* __restrict__ h,
                              const float* __restrict__ W2,
                              const float* __restrict__ b2,
                              const int*   __restrict__ labels,
                              const int*   __restrict__ epoch_ptr,
                              float* __restrict__ probs_out)
{
    __shared__ float w2t[Csz][Hsz];    // W2 transposed: [c][k], 27 KB
    __shared__ float sb2[Csz];
    __shared__ float warpsum[8];

    // Stage W2^T and b2
    for (int i = threadIdx.x; i < Hsz * Csz; i += blockDim.x) {
        int k = i / Csz, c = i % Csz;
        w2t[c][k] = W2[i];
    }
    if (threadIdx.x < Csz) sb2[threadIdx.x] = b2[threadIdx.x];
    __syncthreads();

    const int epoch = *epoch_ptr;      // works for int32 or LE int64 scalar
    const int warp  = threadIdx.x >> 5;
    const int lane  = threadIdx.x & 31;
    const int gwarp = blockIdx.x * 8 + warp;
    const int nwarps = gridDim.x * 8;

    float lsum = 0.0f;

    for (int t = gwarp; t < NTOK; t += nwarps) {
        const float4* hrow = reinterpret_cast<const float4*>(h + (size_t)t * Hsz);
        float acc[Csz];
#pragma unroll
        for (int c = 0; c < Csz; c++) acc[c] = 0.0f;

#pragma unroll
        for (int it = 0; it < Hsz / 128; it++) {   // 6 iters of 32 float4s
            const int k4 = it * 32 + lane;
            const float4 hv = hrow[k4];
#pragma unroll
            for (int c = 0; c < Csz; c++) {
                const float4 wv =
                    reinterpret_cast<const float4*>(&w2t[c][0])[k4];
                acc[c] += hv.x * wv.x + hv.y * wv.y + hv.z * wv.z + hv.w * wv.w;
            }
        }

        // Butterfly reduce each class sum across the warp (all lanes get total)
#pragma unroll
        for (int c = 0; c < Csz; c++) {
            float v = acc[c];
#pragma unroll
            for (int o = 16; o > 0; o >>= 1)
                v += __shfl_xor_sync(0xffffffffu, v, o);
            acc[c] = v + sb2[c];
        }

        // Softmax over C=9 (computed redundantly per lane; deterministic)
        float m = acc[0];
#pragma unroll
        for (int c = 1; c < Csz; c++) m = fmaxf(m, acc[c]);
        float e[Csz];
        float s = 0.0f;
#pragma unroll
        for (int c = 0; c < Csz; c++) { e[c] = expf(acc[c] - m); s += e[c]; }
        const float inv_s = 1.0f / s;

        if (lane < Csz)
            probs_out[(size_t)t * Csz + lane] = e[lane] * inv_s;

        if (lane == 0) {
            const int lbl = labels[t];
            if (lbl != IGNORE_LBL) {
                const float p = e[lbl] * inv_s;
                const float w = (epoch <= 2) ? 1.0f : (p > TAU_F ? 1.0f : 0.0f);
                if (w != 0.0f)
                    lsum += (1.0f - powf(p, QGCE_F)) * (1.0f / QGCE_F);
            }
        }
    }

    if (lane == 0) warpsum[warp] = lsum;
    __syncthreads();
    if (threadIdx.x == 0) {
        float s = 0.0f;
#pragma unroll
        for (int w = 0; w < 8; w++) s += warpsum[w];
        g_partials[blockIdx.x] = s;
    }
}

// ---------------------------------------------------------------------------
// Kernel 3: deterministic fixed-order final reduction of the loss
// ---------------------------------------------------------------------------
__global__ void finalize_loss_kernel(float* __restrict__ loss_out, int nparts)
{
    if (threadIdx.x == 0 && blockIdx.x == 0) {
        float s = 0.0f;
        for (int i = 0; i < nparts; i++) s += g_partials[i];
        *loss_out = s;
    }
}

// ---------------------------------------------------------------------------
// Launch
// Inputs (metadata order): hidden, W1, b1, W2, b2, labels, epoch
// Output: probs [B*S*C] float32, then loss [1] float32
// ---------------------------------------------------------------------------
extern "C" void kernel_launch(void* const* d_in, const int* in_sizes, int n_in,
                              void* d_out, int out_size)
{
    const float* hidden = (const float*)d_in[0];
    const float* W1     = (const float*)d_in[1];
    const float* b1     = (const float*)d_in[2];
    const float* W2     = (const float*)d_in[3];
    const float* b2     = (const float*)d_in[4];
    const int*   labels = (const int*)  d_in[5];
    const int*   epoch  = (const int*)  d_in[6];

    float* out = (float*)d_out;
    const int PROBS_N = NTOK * Csz;   // 294912

    float* probs_dst = out;
    float* loss_dst  = nullptr;
    if (out_size >= PROBS_N + 1) {
        loss_dst = out + PROBS_N;
    } else if (out_size < PROBS_N) {
        // Output doesn't hold probs: sink probs, treat out[0] as loss.
        void* sink = nullptr;
        cudaGetSymbolAddress(&sink, g_probs_sink);
        probs_dst = (float*)sink;
        if (out_size >= 1) loss_dst = out;
    }

    float* hbuf = nullptr;
    cudaGetSymbolAddress((void**)&hbuf, g_h);

    // 1) h = tanh(hidden @ W1 + b1)
    dim3 g1(Hsz / 128, NTOK / 128);   // (6, 256)
    gemm1_tanh_kernel<<<g1, 256>>>(hidden, W1, b1, hbuf);

    // 2) head + softmax + probs + loss partials
    head_softmax_loss_kernel<<<LOSS_BLOCKS, 256>>>(hbuf, W2, b2, labels,
                                                   epoch, probs_dst);

    // 3) deterministic loss finalize
    if (loss_dst != nullptr)
        finalize_loss_kernel<<<1, 32>>>(loss_dst, LOSS_BLOCKS);
}

// round 11
// speedup vs baseline: 1.7803x; 1.7803x over previous
#include <cuda_runtime.h>
#include <cuda_bf16.h>
#include <math.h>
#include <stdint.h>

// Problem shapes (fixed by reference)
#define Bsz   64
#define Ssz   512
#define Esz   768
#define Hsz   768
#define Csz   9
#define NTOK  (Bsz * Ssz)          // 32768 tokens
#define IGNORE_LBL (-100)
#define TAU_F  0.7f
#define QGCE_F 0.7f

// Scratch: h = tanh(hidden @ W1 + b1), [NTOK, H] fp32 (96 MB)
__device__ float g_h[(size_t)NTOK * Hsz];
// W1 transposed + bf16-split: W1T[n][k] = W1[k][n]
__device__ __nv_bfloat16 g_W1T_hi[(size_t)Hsz * Esz];
__device__ __nv_bfloat16 g_W1T_lo[(size_t)Hsz * Esz];
// Fallback probs sink
__device__ float g_probs_sink[(size_t)NTOK * Csz];
// Deterministic loss partials
#define LOSS_BLOCKS 512
__device__ float g_partials[LOSS_BLOCKS];

// ===========================================================================
// Kernel 0: W1T_hi/lo[n][k] = bf16-split of W1[k][n]  (tiled transpose)
// ===========================================================================
__global__ __launch_bounds__(256)
void split_w1_kernel(const float* __restrict__ W1,
                     __nv_bfloat16* __restrict__ hi,
                     __nv_bfloat16* __restrict__ lo)
{
    __shared__ float tile[32][33];
    const int bn = blockIdx.x * 32;       // n base (W1 cols)
    const int bk = blockIdx.y * 32;       // k base (W1 rows)
    const int tx = threadIdx.x, ty = threadIdx.y;   // 32 x 8
#pragma unroll
    for (int r = ty; r < 32; r += 8)
        tile[r][tx] = W1[(size_t)(bk + r) * Hsz + bn + tx];
    __syncthreads();
#pragma unroll
    for (int r = ty; r < 32; r += 8) {
        const float v = tile[tx][r];      // = W1[bk+tx][bn+r]
        const __nv_bfloat16 h = __float2bfloat16_rn(v);
        const float lf = v - __bfloat162float(h);
        hi[(size_t)(bn + r) * Esz + bk + tx] = h;
        lo[(size_t)(bn + r) * Esz + bk + tx] = __float2bfloat16_rn(lf);
    }
}

// ===========================================================================
// mma.sync m16n8k16 bf16 (portable PTX, compiles for baseline compute_103)
// D(m16n8,f32) += A(m16k16,bf16 row) * B(k16n8,bf16 col)
// ===========================================================================
__device__ __forceinline__ void mma16816(float* c, const uint32_t* a,
                                         const uint32_t* b)
{
    asm volatile(
        "mma.sync.aligned.m16n8k16.row.col.f32.bf16.bf16.f32 "
        "{%0,%1,%2,%3}, {%4,%5,%6,%7}, {%8,%9}, {%0,%1,%2,%3};"
        : "+f"(c[0]), "+f"(c[1]), "+f"(c[2]), "+f"(c[3])
        : "r"(a[0]), "r"(a[1]), "r"(a[2]), "r"(a[3]),
          "r"(b[0]), "r"(b[1]));
}

__device__ __forceinline__ uint32_t pack_split_hi(float x, float y,
                                                  uint32_t& lo_out)
{
    const __nv_bfloat16 hx = __float2bfloat16_rn(x);
    const __nv_bfloat16 hy = __float2bfloat16_rn(y);
    const __nv_bfloat16 lx = __float2bfloat16_rn(x - __bfloat162float(hx));
    const __nv_bfloat16 ly = __float2bfloat16_rn(y - __bfloat162float(hy));
    __nv_bfloat162 hp; hp.x = hx; hp.y = hy;
    __nv_bfloat162 lp; lp.x = lx; lp.y = ly;
    lo_out = *reinterpret_cast<uint32_t*>(&lp);
    return *reinterpret_cast<uint32_t*>(&hp);
}

// ===========================================================================
// Kernel 1: h = tanh(hidden @ W1 + b1) via HMMA bf16 3-product split.
// CTA: 128x128 tile, 8 warps (warp tile 64x32), KC=32, 24 stages,
// single smem buffer + register prefetch. Smem row stride 40 bf16 (80B):
// 16B-aligned STS.128 and conflict-free fragment LDS.
// ===========================================================================
#define KC    32
#define NSTG  (Esz / KC)     // 24
#define APAD  40             // bf16 elems per smem row (80 B)

__global__ __launch_bounds__(256)
void gemm1_mma_kernel(const float* __restrict__ A,
                      const __nv_bfloat16* __restrict__ Bhi_g,
                      const __nv_bfloat16* __restrict__ Blo_g,
                      const float* __restrict__ bias,
                      float* __restrict__ Out)
{
    __shared__ __nv_bfloat16 sAhi[128][APAD];
    __shared__ __nv_bfloat16 sAlo[128][APAD];
    __shared__ __nv_bfloat16 sBhi[128][APAD];
    __shared__ __nv_bfloat16 sBlo[128][APAD];

    const int tid    = threadIdx.x;
    const int wid    = tid >> 5;
    const int lane   = tid & 31;
    const int warp_m = wid >> 2;       // 0..1  (64-row halves)
    const int warp_n = wid & 3;        // 0..3  (32-col quarters)

    const int m0 = blockIdx.y * 128;
    const int n0 = blockIdx.x * 128;

    const float* Ab = A + (size_t)m0 * Esz;
    const __nv_bfloat16* Bh = Bhi_g + (size_t)n0 * Esz;
    const __nv_bfloat16* Bl = Blo_g + (size_t)n0 * Esz;

    float acc[4][4][4];
#pragma unroll
    for (int mt = 0; mt < 4; mt++)
#pragma unroll
        for (int nt = 0; nt < 4; nt++)
#pragma unroll
            for (int r = 0; r < 4; r++) acc[mt][nt][r] = 0.0f;

    // Prefetch registers for next stage
    float4 pa[4];
    uint4  pbh[2], pbl[2];

    // A load map: 1024 float4/stage; u = i*256+tid; row=u>>3; c4=u&7
    // B load map: 512 uint4 per (hi|lo); u = i*256+tid; row=u>>2; c8=u&3
#pragma unroll
    for (int i = 0; i < 4; i++) {
        const int u = i * 256 + tid;
        pa[i] = *reinterpret_cast<const float4*>(
            Ab + (size_t)(u >> 3) * Esz + (u & 7) * 4);
    }
#pragma unroll
    for (int i = 0; i < 2; i++) {
        const int u = i * 256 + tid;
        pbh[i] = *reinterpret_cast<const uint4*>(
            Bh + (size_t)(u >> 2) * Esz + (u & 3) * 8);
        pbl[i] = *reinterpret_cast<const uint4*>(
            Bl + (size_t)(u >> 2) * Esz + (u & 3) * 8);
    }

    for (int kt = 0; kt < NSTG; ++kt) {
        // --- Stage prefetched registers into shared memory ---
#pragma unroll
        for (int i = 0; i < 4; i++) {
            const int u   = i * 256 + tid;
            const int row = u >> 3;
            const int c   = (u & 7) * 4;
            uint32_t l01, l23;
            const uint32_t h01 = pack_split_hi(pa[i].x, pa[i].y, l01);
            const uint32_t h23 = pack_split_hi(pa[i].z, pa[i].w, l23);
            *reinterpret_cast<uint2*>(&sAhi[row][c]) = make_uint2(h01, h23);
            *reinterpret_cast<uint2*>(&sAlo[row][c]) = make_uint2(l01, l23);
        }
#pragma unroll
        for (int i = 0; i < 2; i++) {
            const int u   = i * 256 + tid;
            const int row = u >> 2;
            const int c   = (u & 3) * 8;
            *reinterpret_cast<uint4*>(&sBhi[row][c]) = pbh[i];
            *reinterpret_cast<uint4*>(&sBlo[row][c]) = pbl[i];
        }
        __syncthreads();

        // --- Prefetch next stage from global (overlaps compute) ---
        if (kt + 1 < NSTG) {
            const int k0n = (kt + 1) * KC;
#pragma unroll
            for (int i = 0; i < 4; i++) {
                const int u = i * 256 + tid;
                pa[i] = *reinterpret_cast<const float4*>(
                    Ab + (size_t)(u >> 3) * Esz + k0n + (u & 7) * 4);
            }
#pragma unroll
            for (int i = 0; i < 2; i++) {
                const int u = i * 256 + tid;
                pbh[i] = *reinterpret_cast<const uint4*>(
                    Bh + (size_t)(u >> 2) * Esz + k0n + (u & 3) * 8);
                pbl[i] = *reinterpret_cast<const uint4*>(
                    Bl + (size_t)(u >> 2) * Esz + k0n + (u & 3) * 8);
            }
        }

        // --- Compute: 2 x k16 steps, 3 products each ---
        const int r  = lane >> 2;
        const int cp = (lane & 3) * 2;
#pragma unroll
        for (int ks = 0; ks < 2; ks++) {
            const int kk = ks * 16;
            uint32_t ah[4][4], bh[4][2], bl[4][2], al[4][4];

#pragma unroll
            for (int mt = 0; mt < 4; mt++) {
                const int rb = warp_m * 64 + mt * 16;
                ah[mt][0] = *reinterpret_cast<const uint32_t*>(&sAhi[rb + r][kk + cp]);
                ah[mt][1] = *reinterpret_cast<const uint32_t*>(&sAhi[rb + r + 8][kk + cp]);
                ah[mt][2] = *reinterpret_cast<const uint32_t*>(&sAhi[rb + r][kk + 8 + cp]);
                ah[mt][3] = *reinterpret_cast<const uint32_t*>(&sAhi[rb + r + 8][kk + 8 + cp]);
            }
#pragma unroll
            for (int nt = 0; nt < 4; nt++) {
                const int nb = warp_n * 32 + nt * 8;
                bh[nt][0] = *reinterpret_cast<const uint32_t*>(&sBhi[nb + r][kk + cp]);
                bh[nt][1] = *reinterpret_cast<const uint32_t*>(&sBhi[nb + r][kk + 8 + cp]);
            }
            // hi * hi
#pragma unroll
            for (int mt = 0; mt < 4; mt++)
#pragma unroll
                for (int nt = 0; nt < 4; nt++)
                    mma16816(acc[mt][nt], ah[mt], bh[nt]);

            // hi * lo
#pragma unroll
            for (int nt = 0; nt < 4; nt++) {
                const int nb = warp_n * 32 + nt * 8;
                bl[nt][0] = *reinterpret_cast<const uint32_t*>(&sBlo[nb + r][kk + cp]);
                bl[nt][1] = *reinterpret_cast<const uint32_t*>(&sBlo[nb + r][kk + 8 + cp]);
            }
#pragma unroll
            for (int mt = 0; mt < 4; mt++)
#pragma unroll
                for (int nt = 0; nt < 4; nt++)
                    mma16816(acc[mt][nt], ah[mt], bl[nt]);

            // lo * hi
#pragma unroll
            for (int mt = 0; mt < 4; mt++) {
                const int rb = warp_m * 64 + mt * 16;
                al[mt][0] = *reinterpret_cast<const uint32_t*>(&sAlo[rb + r][kk + cp]);
                al[mt][1] = *reinterpret_cast<const uint32_t*>(&sAlo[rb + r + 8][kk + cp]);
                al[mt][2] = *reinterpret_cast<const uint32_t*>(&sAlo[rb + r][kk + 8 + cp]);
                al[mt][3] = *reinterpret_cast<const uint32_t*>(&sAlo[rb + r + 8][kk + 8 + cp]);
            }
#pragma unroll
            for (int mt = 0; mt < 4; mt++)
#pragma unroll
                for (int nt = 0; nt < 4; nt++)
                    mma16816(acc[mt][nt], al[mt], bh[nt]);
        }
        __syncthreads();
    }

    // --- Epilogue: bias + tanh ---
    const int r  = lane >> 2;
    const int cp = (lane & 3) * 2;
#pragma unroll
    for (int nt = 0; nt < 4; nt++) {
        const int col = n0 + warp_n * 32 + nt * 8 + cp;
        const float b0 = bias[col];
        const float b1 = bias[col + 1];
#pragma unroll
        for (int mt = 0; mt < 4; mt++) {
            const int row0 = m0 + warp_m * 64 + mt * 16 + r;
            float2 o0, o1;
            o0.x = tanhf(acc[mt][nt][0] + b0);
            o0.y = tanhf(acc[mt][nt][1] + b1);
            o1.x = tanhf(acc[mt][nt][2] + b0);
            o1.y = tanhf(acc[mt][nt][3] + b1);
            *reinterpret_cast<float2*>(Out + (size_t)row0 * Hsz + col)       = o0;
            *reinterpret_cast<float2*>(Out + (size_t)(row0 + 8) * Hsz + col) = o1;
        }
    }
}

// ===========================================================================
// Kernel 2: logits = h @ W2 + b2; softmax C=9; probs; deterministic partials.
// ===========================================================================
__global__ __launch_bounds__(256)
void head_softmax_loss_kernel(const float* __restrict__ h,
                              const float* __restrict__ W2,
                              const float* __restrict__ b2,
                              const int*   __restrict__ labels,
                              const int*   __restrict__ epoch_ptr,
                              float* __restrict__ probs_out)
{
    __shared__ float w2t[Csz][Hsz];    // W2 transposed: [c][k], 27 KB
    __shared__ float sb2[Csz];
    __shared__ float warpsum[8];

    for (int i = threadIdx.x; i < Hsz * Csz; i += blockDim.x) {
        int k = i / Csz, c = i % Csz;
        w2t[c][k] = W2[i];
    }
    if (threadIdx.x < Csz) sb2[threadIdx.x] = b2[threadIdx.x];
    __syncthreads();

    const int epoch = *epoch_ptr;
    const int warp  = threadIdx.x >> 5;
    const int lane  = threadIdx.x & 31;
    const int gwarp = blockIdx.x * 8 + warp;
    const int nwarps = gridDim.x * 8;

    float lsum = 0.0f;

    for (int t = gwarp; t < NTOK; t += nwarps) {
        const float4* hrow = reinterpret_cast<const float4*>(h + (size_t)t * Hsz);
        float acc[Csz];
#pragma unroll
        for (int c = 0; c < Csz; c++) acc[c] = 0.0f;

#pragma unroll
        for (int it = 0; it < Hsz / 128; it++) {
            const int k4 = it * 32 + lane;
            const float4 hv = hrow[k4];
#pragma unroll
            for (int c = 0; c < Csz; c++) {
                const float4 wv = reinterpret_cast<const float4*>(&w2t[c][0])[k4];
                acc[c] += hv.x * wv.x + hv.y * wv.y + hv.z * wv.z + hv.w * wv.w;
            }
        }

#pragma unroll
        for (int c = 0; c < Csz; c++) {
            float v = acc[c];
#pragma unroll
            for (int o = 16; o > 0; o >>= 1)
                v += __shfl_xor_sync(0xffffffffu, v, o);
            acc[c] = v + sb2[c];
        }

        float m = acc[0];
#pragma unroll
        for (int c = 1; c < Csz; c++) m = fmaxf(m, acc[c]);
        float e[Csz];
        float s = 0.0f;
#pragma unroll
        for (int c = 0; c < Csz; c++) { e[c] = expf(acc[c] - m); s += e[c]; }
        const float inv_s = 1.0f / s;

        if (lane < Csz)
            probs_out[(size_t)t * Csz + lane] = e[lane] * inv_s;

        if (lane == 0) {
            const int lbl = labels[t];
            if (lbl != IGNORE_LBL) {
                const float p = e[lbl] * inv_s;
                const float w = (epoch <= 2) ? 1.0f : (p > TAU_F ? 1.0f : 0.0f);
                if (w != 0.0f)
                    lsum += (1.0f - powf(p, QGCE_F)) * (1.0f / QGCE_F);
            }
        }
    }

    if (lane == 0) warpsum[warp] = lsum;
    __syncthreads();
    if (threadIdx.x == 0) {
        float s = 0.0f;
#pragma unroll
        for (int w = 0; w < 8; w++) s += warpsum[w];
        g_partials[blockIdx.x] = s;
    }
}

// ===========================================================================
// Kernel 3: deterministic fixed-order final loss reduction
// ===========================================================================
__global__ void finalize_loss_kernel(float* __restrict__ loss_out, int nparts)
{
    if (threadIdx.x == 0 && blockIdx.x == 0) {
        float s = 0.0f;
        for (int i = 0; i < nparts; i++) s += g_partials[i];
        *loss_out = s;
    }
}

// ===========================================================================
// Launch. Inputs: hidden, W1, b1, W2, b2, labels, epoch.
// Output: probs [B*S*C] fp32, then loss [1] fp32.
// ===========================================================================
extern "C" void kernel_launch(void* const* d_in, const int* in_sizes, int n_in,
                              void* d_out, int out_size)
{
    const float* hidden = (const float*)d_in[0];
    const float* W1     = (const float*)d_in[1];
    const float* b1     = (const float*)d_in[2];
    const float* W2     = (const float*)d_in[3];
    const float* b2     = (const float*)d_in[4];
    const int*   labels = (const int*)  d_in[5];
    const int*   epoch  = (const int*)  d_in[6];

    float* out = (float*)d_out;
    const int PROBS_N = NTOK * Csz;   // 294912

    float* probs_dst = out;
    float* loss_dst  = nullptr;
    if (out_size >= PROBS_N + 1) {
        loss_dst = out + PROBS_N;
    } else if (out_size < PROBS_N) {
        void* sink = nullptr;
        cudaGetSymbolAddress(&sink, g_probs_sink);
        probs_dst = (float*)sink;
        if (out_size >= 1) loss_dst = out;
    }

    float* hbuf = nullptr;
    cudaGetSymbolAddress((void**)&hbuf, g_h);
    __nv_bfloat16* w1t_hi = nullptr;
    __nv_bfloat16* w1t_lo = nullptr;
    cudaGetSymbolAddress((void**)&w1t_hi, g_W1T_hi);
    cudaGetSymbolAddress((void**)&w1t_lo, g_W1T_lo);

    // 0) transpose + bf16-split W1
    split_w1_kernel<<<dim3(Hsz / 32, Esz / 32), dim3(32, 8)>>>(W1, w1t_hi, w1t_lo);

    // 1) h = tanh(hidden @ W1 + b1), HMMA bf16 3-product
    dim3 g1(Hsz / 128, NTOK / 128);   // (6, 256)
    gemm1_mma_kernel<<<g1, 256>>>(hidden, w1t_hi, w1t_lo, b1, hbuf);

    // 2) head + softmax + probs + loss partials
    head_softmax_loss_kernel<<<LOSS_BLOCKS, 256>>>(hbuf, W2, b2, labels,
                                                   epoch, probs_dst);

    // 3) deterministic loss finalize
    if (loss_dst != nullptr)
        finalize_loss_kernel<<<1, 32>>>(loss_dst, LOSS_BLOCKS);
}

// round 13
// speedup vs baseline: 1.8487x; 1.0385x over previous
#include <cuda_runtime.h>
#include <cuda_bf16.h>
#include <math.h>
#include <stdint.h>

// Problem shapes (fixed by reference)
#define Bsz   64
#define Ssz   512
#define Esz   768
#define Hsz   768
#define Csz   9
#define NTOK  (Bsz * Ssz)          // 32768 tokens
#define IGNORE_LBL (-100)
#define TAU_F  0.7f
#define QGCE_F 0.7f

// Scratch buffers (static device memory; no runtime alloc)
__device__ float g_h[(size_t)NTOK * Hsz];                  // 96 MB
__device__ __nv_bfloat16 g_A_hi[(size_t)NTOK * Esz];       // 48 MB
__device__ __nv_bfloat16 g_A_lo[(size_t)NTOK * Esz];       // 48 MB
__device__ __nv_bfloat16 g_W1T_hi[(size_t)Hsz * Esz];
__device__ __nv_bfloat16 g_W1T_lo[(size_t)Hsz * Esz];
__device__ float g_probs_sink[(size_t)NTOK * Csz];
#define LOSS_BLOCKS 512
__device__ float g_partials[LOSS_BLOCKS];

// ===========================================================================
// Common helpers
// ===========================================================================
__device__ __forceinline__ uint32_t pack_split_hi(float x, float y,
                                                  uint32_t& lo_out)
{
    const __nv_bfloat16 hx = __float2bfloat16_rn(x);
    const __nv_bfloat16 hy = __float2bfloat16_rn(y);
    const __nv_bfloat16 lx = __float2bfloat16_rn(x - __bfloat162float(hx));
    const __nv_bfloat16 ly = __float2bfloat16_rn(y - __bfloat162float(hy));
    __nv_bfloat162 hp; hp.x = hx; hp.y = hy;
    __nv_bfloat162 lp; lp.x = lx; lp.y = ly;
    lo_out = *reinterpret_cast<uint32_t*>(&lp);
    return *reinterpret_cast<uint32_t*>(&hp);
}

__device__ __forceinline__ void mma16816(float* c, const uint32_t* a,
                                         const uint32_t* b)
{
    asm volatile(
        "mma.sync.aligned.m16n8k16.row.col.f32.bf16.bf16.f32 "
        "{%0,%1,%2,%3}, {%4,%5,%6,%7}, {%8,%9}, {%0,%1,%2,%3};"
        : "+f"(c[0]), "+f"(c[1]), "+f"(c[2]), "+f"(c[3])
        : "r"(a[0]), "r"(a[1]), "r"(a[2]), "r"(a[3]),
          "r"(b[0]), "r"(b[1]));
}

__device__ __forceinline__ void ldsm_x4(uint32_t& r0, uint32_t& r1,
                                        uint32_t& r2, uint32_t& r3,
                                        uint32_t saddr)
{
    asm volatile("ldmatrix.sync.aligned.m8n8.x4.shared.b16 {%0,%1,%2,%3}, [%4];"
                 : "=r"(r0), "=r"(r1), "=r"(r2), "=r"(r3) : "r"(saddr));
}

__device__ __forceinline__ void cp_async16(uint32_t dst, const void* src)
{
    asm volatile("cp.async.cg.shared.global [%0], [%1], 16;"
                 :: "r"(dst), "l"(src));
}
#define CP_ASYNC_COMMIT() asm volatile("cp.async.commit_group;" ::: "memory")
#define CP_ASYNC_WAIT1()  asm volatile("cp.async.wait_group 1;" ::: "memory")
#define CP_ASYNC_WAIT0()  asm volatile("cp.async.wait_group 0;" ::: "memory")

// ===========================================================================
// Kernel 0a: elementwise bf16-split of A (hidden): hi + lo
// ===========================================================================
__global__ __launch_bounds__(256)
void split_a_kernel(const float4* __restrict__ A4,
                    uint2* __restrict__ hi2,
                    uint2* __restrict__ lo2, int n4)
{
    const int stride = gridDim.x * blockDim.x;
    for (int i = blockIdx.x * blockDim.x + threadIdx.x; i < n4; i += stride) {
        const float4 v = A4[i];
        uint32_t l01, l23;
        const uint32_t h01 = pack_split_hi(v.x, v.y, l01);
        const uint32_t h23 = pack_split_hi(v.z, v.w, l23);
        hi2[i] = make_uint2(h01, h23);
        lo2[i] = make_uint2(l01, l23);
    }
}

// ===========================================================================
// Kernel 0b: W1T_hi/lo[n][k] = bf16-split of W1[k][n]  (tiled transpose)
// ===========================================================================
__global__ __launch_bounds__(256)
void split_w1_kernel(const float* __restrict__ W1,
                     __nv_bfloat16* __restrict__ hi,
                     __nv_bfloat16* __restrict__ lo)
{
    __shared__ float tile[32][33];
    const int bn = blockIdx.x * 32;
    const int bk = blockIdx.y * 32;
    const int tx = threadIdx.x, ty = threadIdx.y;   // 32 x 8
#pragma unroll
    for (int r = ty; r < 32; r += 8)
        tile[r][tx] = W1[(size_t)(bk + r) * Hsz + bn + tx];
    __syncthreads();
#pragma unroll
    for (int r = ty; r < 32; r += 8) {
        const float v = tile[tx][r];      // = W1[bk+tx][bn+r]
        const __nv_bfloat16 h = __float2bfloat16_rn(v);
        const float lf = v - __bfloat162float(h);
        hi[(size_t)(bn + r) * Esz + bk + tx] = h;
        lo[(size_t)(bn + r) * Esz + bk + tx] = __float2bfloat16_rn(lf);
    }
}

// ===========================================================================
// Kernel 1: h = tanh(hidden @ W1 + b1), HMMA bf16 3-product, cp.async
// double-buffered smem + ldmatrix fragments.
// CTA 128x128, 8 warps (warp tile 64x32), KC=32, 24 stages.
// Smem: 4 operand tiles x 2 stages, row stride 40 bf16 (80 B) ->
// conflict-free LDSM and 16B-aligned cp.async.
// ===========================================================================
#define KC    32
#define NSTG  (Esz / KC)     // 24
#define APAD  40             // bf16 elems per smem row
#define TILE_B (128 * APAD * 2)            // 10240 bytes per tile
#define GEMM_SMEM (8 * TILE_B)             // 81920 bytes

__global__ __launch_bounds__(256, 2)
void gemm1_mma_kernel(const __nv_bfloat16* __restrict__ Ahi_g,
                      const __nv_bfloat16* __restrict__ Alo_g,
                      const __nv_bfloat16* __restrict__ Bhi_g,
                      const __nv_bfloat16* __restrict__ Blo_g,
                      const float* __restrict__ bias,
                      float* __restrict__ Out)
{
    extern __shared__ __nv_bfloat16 smem_g[];
    const uint32_t smem_u32 = (uint32_t)__cvta_generic_to_shared(smem_g);

    const int tid    = threadIdx.x;
    const int wid    = tid >> 5;
    const int lane   = tid & 31;
    const int warp_m = wid >> 2;       // 0..1
    const int warp_n = wid & 3;        // 0..3

    const int m0 = blockIdx.y * 128;
    const int n0 = blockIdx.x * 128;

    const __nv_bfloat16* gsrc[4] = {
        Ahi_g + (size_t)m0 * Esz,
        Alo_g + (size_t)m0 * Esz,
        Bhi_g + (size_t)n0 * Esz,
        Blo_g + (size_t)n0 * Esz
    };

    // cp.async mapping: per tile 512 x 16B chunks; 2 per thread
    const int crow0 = tid >> 2;            // chunk i=0: rows 0..63
    const int ccol  = (tid & 3) * 8;       // elem offset (16B chunks)
    const int crow1 = crow0 + 64;          // chunk i=1

    // Issue one stage's cp.async (32 KB)
    auto issue_stage = [&](int kt) {
        const int buf = kt & 1;
        const int k0  = kt * KC;
#pragma unroll
        for (int t = 0; t < 4; t++) {
            const uint32_t sbase = smem_u32 + (uint32_t)(t * 2 + buf) * TILE_B;
            cp_async16(sbase + crow0 * (APAD * 2) + ccol * 2,
                       gsrc[t] + (size_t)crow0 * Esz + k0 + ccol);
            cp_async16(sbase + crow1 * (APAD * 2) + ccol * 2,
                       gsrc[t] + (size_t)crow1 * Esz + k0 + ccol);
        }
        CP_ASYNC_COMMIT();
    };

    float acc[4][4][4];
#pragma unroll
    for (int mt = 0; mt < 4; mt++)
#pragma unroll
        for (int nt = 0; nt < 4; nt++)
#pragma unroll
            for (int r = 0; r < 4; r++) acc[mt][nt][r] = 0.0f;

    // ldmatrix per-lane row/col offsets
    const int lrow  = (lane & 7) + ((lane >> 3) & 1) * 8;  // row within 16
    const int lcol8 = (lane >> 4) * 8;                     // 0 or 8 (k)

    issue_stage(0);
    issue_stage(1);

    for (int kt = 0; kt < NSTG; ++kt) {
        const int buf = kt & 1;
        if (kt + 1 < NSTG) { CP_ASYNC_WAIT1(); } else { CP_ASYNC_WAIT0(); }
        __syncthreads();

        const uint32_t bAhi = smem_u32 + (uint32_t)(0 * 2 + buf) * TILE_B;
        const uint32_t bAlo = smem_u32 + (uint32_t)(1 * 2 + buf) * TILE_B;
        const uint32_t bBhi = smem_u32 + (uint32_t)(2 * 2 + buf) * TILE_B;
        const uint32_t bBlo = smem_u32 + (uint32_t)(3 * 2 + buf) * TILE_B;

#pragma unroll
        for (int ks = 0; ks < 2; ks++) {
            const int kk = ks * 16;
            const uint32_t coff = (uint32_t)(kk + lcol8) * 2;

            uint32_t ah[4][4], al[4][4], bb[4][2];

            // A-hi fragments: 4 x ldmatrix.x4 (one per mt)
#pragma unroll
            for (int mt = 0; mt < 4; mt++) {
                const uint32_t a = bAhi +
                    (uint32_t)(warp_m * 64 + mt * 16 + lrow) * (APAD * 2) + coff;
                ldsm_x4(ah[mt][0], ah[mt][1], ah[mt][2], ah[mt][3], a);
            }
            // B-hi fragments: 2 x ldmatrix.x4 (each covers nt pair)
#pragma unroll
            for (int p = 0; p < 2; p++) {
                const uint32_t a = bBhi +
                    (uint32_t)(warp_n * 32 + p * 16 + lrow) * (APAD * 2) + coff;
                ldsm_x4(bb[2 * p][0], bb[2 * p + 1][0],
                        bb[2 * p][1], bb[2 * p + 1][1], a);
            }
            // hi * hi
#pragma unroll
            for (int mt = 0; mt < 4; mt++)
#pragma unroll
                for (int nt = 0; nt < 4; nt++)
                    mma16816(acc[mt][nt], ah[mt], bb[nt]);

            // A-lo fragments, then lo * hi
#pragma unroll
            for (int mt = 0; mt < 4; mt++) {
                const uint32_t a = bAlo +
                    (uint32_t)(warp_m * 64 + mt * 16 + lrow) * (APAD * 2) + coff;
                ldsm_x4(al[mt][0], al[mt][1], al[mt][2], al[mt][3], a);
            }
#pragma unroll
            for (int mt = 0; mt < 4; mt++)
#pragma unroll
                for (int nt = 0; nt < 4; nt++)
                    mma16816(acc[mt][nt], al[mt], bb[nt]);

            // B-lo fragments (reuse bb), then hi * lo
#pragma unroll
            for (int p = 0; p < 2; p++) {
                const uint32_t a = bBlo +
                    (uint32_t)(warp_n * 32 + p * 16 + lrow) * (APAD * 2) + coff;
                ldsm_x4(bb[2 * p][0], bb[2 * p + 1][0],
                        bb[2 * p][1], bb[2 * p + 1][1], a);
            }
#pragma unroll
            for (int mt = 0; mt < 4; mt++)
#pragma unroll
                for (int nt = 0; nt < 4; nt++)
                    mma16816(acc[mt][nt], ah[mt], bb[nt]);
        }
        __syncthreads();
        if (kt + 2 < NSTG) issue_stage(kt + 2);
    }

    // --- Epilogue: bias + tanh ---
    const int r  = lane >> 2;
    const int cp = (lane & 3) * 2;
#pragma unroll
    for (int nt = 0; nt < 4; nt++) {
        const int col = n0 + warp_n * 32 + nt * 8 + cp;
        const float b0 = bias[col];
        const float b1 = bias[col + 1];
#pragma unroll
        for (int mt = 0; mt < 4; mt++) {
            const int row0 = m0 + warp_m * 64 + mt * 16 + r;
            float2 o0, o1;
            o0.x = tanhf(acc[mt][nt][0] + b0);
            o0.y = tanhf(acc[mt][nt][1] + b1);
            o1.x = tanhf(acc[mt][nt][2] + b0);
            o1.y = tanhf(acc[mt][nt][3] + b1);
            *reinterpret_cast<float2*>(Out + (size_t)row0 * Hsz + col)       = o0;
            *reinterpret_cast<float2*>(Out + (size_t)(row0 + 8) * Hsz + col) = o1;
        }
    }
}

// ===========================================================================
// Kernel 2: logits = h @ W2 + b2; softmax C=9; probs; deterministic partials.
// ===========================================================================
__global__ __launch_bounds__(256)
void head_softmax_loss_kernel(const float* __restrict__ h,
                              const float* __restrict__ W2,
                              const float* __restrict__ b2,
                              const int*   __restrict__ labels,
                              const int*   __restrict__ epoch_ptr,
                              float* __restrict__ probs_out)
{
    __shared__ float w2t[Csz][Hsz];    // W2 transposed: [c][k], 27 KB
    __shared__ float sb2[Csz];
    __shared__ float warpsum[8];

    for (int i = threadIdx.x; i < Hsz * Csz; i += blockDim.x) {
        int k = i / Csz, c = i % Csz;
        w2t[c][k] = W2[i];
    }
    if (threadIdx.x < Csz) sb2[threadIdx.x] = b2[threadIdx.x];
    __syncthreads();

    const int epoch = *epoch_ptr;
    const int warp  = threadIdx.x >> 5;
    const int lane  = threadIdx.x & 31;
    const int gwarp = blockIdx.x * 8 + warp;
    const int nwarps = gridDim.x * 8;

    float lsum = 0.0f;

    for (int t = gwarp; t < NTOK; t += nwarps) {
        const float4* hrow = reinterpret_cast<const float4*>(h + (size_t)t * Hsz);
        float acc[Csz];
#pragma unroll
        for (int c = 0; c < Csz; c++) acc[c] = 0.0f;

#pragma unroll
        for (int it = 0; it < Hsz / 128; it++) {
            const int k4 = it * 32 + lane;
            const float4 hv = hrow[k4];
#pragma unroll
            for (int c = 0; c < Csz; c++) {
                const float4 wv = reinterpret_cast<const float4*>(&w2t[c][0])[k4];
                acc[c] += hv.x * wv.x + hv.y * wv.y + hv.z * wv.z + hv.w * wv.w;
            }
        }

#pragma unroll
        for (int c = 0; c < Csz; c++) {
            float v = acc[c];
#pragma unroll
            for (int o = 16; o > 0; o >>= 1)
                v += __shfl_xor_sync(0xffffffffu, v, o);
            acc[c] = v + sb2[c];
        }

        float m = acc[0];
#pragma unroll
        for (int c = 1; c < Csz; c++) m = fmaxf(m, acc[c]);
        float e[Csz];
        float s = 0.0f;
#pragma unroll
        for (int c = 0; c < Csz; c++) { e[c] = expf(acc[c] - m); s += e[c]; }
        const float inv_s = 1.0f / s;

        if (lane < Csz)
            probs_out[(size_t)t * Csz + lane] = e[lane] * inv_s;

        if (lane == 0) {
            const int lbl = labels[t];
            if (lbl != IGNORE_LBL) {
                const float p = e[lbl] * inv_s;
                const float w = (epoch <= 2) ? 1.0f : (p > TAU_F ? 1.0f : 0.0f);
                if (w != 0.0f)
                    lsum += (1.0f - powf(p, QGCE_F)) * (1.0f / QGCE_F);
            }
        }
    }

    if (lane == 0) warpsum[warp] = lsum;
    __syncthreads();
    if (threadIdx.x == 0) {
        float s = 0.0f;
#pragma unroll
        for (int w = 0; w < 8; w++) s += warpsum[w];
        g_partials[blockIdx.x] = s;
    }
}

// ===========================================================================
// Kernel 3: deterministic (fixed-order tree) final loss reduction
// ===========================================================================
__global__ __launch_bounds__(256)
void finalize_loss_kernel(float* __restrict__ loss_out)
{
    __shared__ float s[256];
    const int t = threadIdx.x;
    s[t] = g_partials[t] + g_partials[t + 256];
    __syncthreads();
#pragma unroll
    for (int o = 128; o > 0; o >>= 1) {
        if (t < o) s[t] += s[t + o];
        __syncthreads();
    }
    if (t == 0) *loss_out = s[0];
}

// ===========================================================================
// Launch. Inputs: hidden, W1, b1, W2, b2, labels, epoch.
// Output: probs [B*S*C] fp32, then loss [1] fp32.
// ===========================================================================
extern "C" void kernel_launch(void* const* d_in, const int* in_sizes, int n_in,
                              void* d_out, int out_size)
{
    const float* hidden = (const float*)d_in[0];
    const float* W1     = (const float*)d_in[1];
    const float* b1     = (const float*)d_in[2];
    const float* W2     = (const float*)d_in[3];
    const float* b2     = (const float*)d_in[4];
    const int*   labels = (const int*)  d_in[5];
    const int*   epoch  = (const int*)  d_in[6];

    float* out = (float*)d_out;
    const int PROBS_N = NTOK * Csz;   // 294912

    float* probs_dst = out;
    float* loss_dst  = nullptr;
    if (out_size >= PROBS_N + 1) {
        loss_dst = out + PROBS_N;
    } else if (out_size < PROBS_N) {
        void* sink = nullptr;
        cudaGetSymbolAddress(&sink, g_probs_sink);
        probs_dst = (float*)sink;
        if (out_size >= 1) loss_dst = out;
    }

    float* hbuf = nullptr;
    cudaGetSymbolAddress((void**)&hbuf, g_h);
    __nv_bfloat16 *a_hi = nullptr, *a_lo = nullptr, *w1t_hi = nullptr, *w1t_lo = nullptr;
    cudaGetSymbolAddress((void**)&a_hi, g_A_hi);
    cudaGetSymbolAddress((void**)&a_lo, g_A_lo);
    cudaGetSymbolAddress((void**)&w1t_hi, g_W1T_hi);
    cudaGetSymbolAddress((void**)&w1t_lo, g_W1T_lo);

    // 0) split A and W1 to bf16 hi/lo
    const int n4 = NTOK * Esz / 4;    // 6291456 float4s
    split_a_kernel<<<6144, 256>>>((const float4*)hidden,
                                  (uint2*)a_hi, (uint2*)a_lo, n4);
    split_w1_kernel<<<dim3(Hsz / 32, Esz / 32), dim3(32, 8)>>>(W1, w1t_hi, w1t_lo);

    // 1) h = tanh(hidden @ W1 + b1): cp.async + ldmatrix + HMMA 3-product
    cudaFuncSetAttribute(gemm1_mma_kernel,
                         cudaFuncAttributeMaxDynamicSharedMemorySize, GEMM_SMEM);
    dim3 g1(Hsz / 128, NTOK / 128);   // (6, 256)
    gemm1_mma_kernel<<<g1, 256, GEMM_SMEM>>>(a_hi, a_lo, w1t_hi, w1t_lo, b1, hbuf);

    // 2) head + softmax + probs + loss partials
    head_softmax_loss_kernel<<<LOSS_BLOCKS, 256>>>(hbuf, W2, b2, labels,
                                                   epoch, probs_dst);

    // 3) deterministic loss finalize
    if (loss_dst != nullptr)
        finalize_loss_kernel<<<1, 256>>>(loss_dst);
}

// round 14
// speedup vs baseline: 2.1365x; 1.1557x over previous
#include <cuda_runtime.h>
#include <cuda_bf16.h>
#include <math.h>
#include <stdint.h>

// Problem shapes (fixed by reference)
#define Bsz   64
#define Ssz   512
#define Esz   768
#define Hsz   768
#define Csz   9
#define NTOK  (Bsz * Ssz)          // 32768 tokens
#define IGNORE_LBL (-100)
#define TAU_F  0.7f
#define QGCE_F 0.7f

// Scratch buffers (static device memory; no runtime alloc)
__device__ float g_h[(size_t)NTOK * Hsz];                  // 96 MB
__device__ __nv_bfloat16 g_A_hi[(size_t)NTOK * Esz];       // 48 MB
__device__ __nv_bfloat16 g_A_lo[(size_t)NTOK * Esz];       // 48 MB
__device__ __nv_bfloat16 g_W1T_hi[(size_t)Hsz * Esz];
__device__ __nv_bfloat16 g_W1T_lo[(size_t)Hsz * Esz];
__device__ float g_probs_sink[(size_t)NTOK * Csz];
#define LOSS_BLOCKS 512
__device__ float g_partials[LOSS_BLOCKS];

// ===========================================================================
// Common helpers
// ===========================================================================
__device__ __forceinline__ uint32_t pack_split_hi(float x, float y,
                                                  uint32_t& lo_out)
{
    const __nv_bfloat16 hx = __float2bfloat16_rn(x);
    const __nv_bfloat16 hy = __float2bfloat16_rn(y);
    const __nv_bfloat16 lx = __float2bfloat16_rn(x - __bfloat162float(hx));
    const __nv_bfloat16 ly = __float2bfloat16_rn(y - __bfloat162float(hy));
    __nv_bfloat162 hp; hp.x = hx; hp.y = hy;
    __nv_bfloat162 lp; lp.x = lx; lp.y = ly;
    lo_out = *reinterpret_cast<uint32_t*>(&lp);
    return *reinterpret_cast<uint32_t*>(&hp);
}

__device__ __forceinline__ void mma16816(float* c, const uint32_t* a,
                                         const uint32_t* b)
{
    asm volatile(
        "mma.sync.aligned.m16n8k16.row.col.f32.bf16.bf16.f32 "
        "{%0,%1,%2,%3}, {%4,%5,%6,%7}, {%8,%9}, {%0,%1,%2,%3};"
        : "+f"(c[0]), "+f"(c[1]), "+f"(c[2]), "+f"(c[3])
        : "r"(a[0]), "r"(a[1]), "r"(a[2]), "r"(a[3]),
          "r"(b[0]), "r"(b[1]));
}

__device__ __forceinline__ void ldsm_x4(uint32_t& r0, uint32_t& r1,
                                        uint32_t& r2, uint32_t& r3,
                                        uint32_t saddr)
{
    asm volatile("ldmatrix.sync.aligned.m8n8.x4.shared.b16 {%0,%1,%2,%3}, [%4];"
                 : "=r"(r0), "=r"(r1), "=r"(r2), "=r"(r3) : "r"(saddr));
}

__device__ __forceinline__ void cp_async16(uint32_t dst, const void* src)
{
    asm volatile("cp.async.cg.shared.global [%0], [%1], 16;"
                 :: "r"(dst), "l"(src));
}
#define CP_ASYNC_COMMIT() asm volatile("cp.async.commit_group;" ::: "memory")
#define CP_ASYNC_WAIT1()  asm volatile("cp.async.wait_group 1;" ::: "memory")
#define CP_ASYNC_WAIT0()  asm volatile("cp.async.wait_group 0;" ::: "memory")

// ===========================================================================
// Kernel 0a: elementwise bf16-split of A (hidden): hi + lo
// ===========================================================================
__global__ __launch_bounds__(256)
void split_a_kernel(const float4* __restrict__ A4,
                    uint2* __restrict__ hi2,
                    uint2* __restrict__ lo2, int n4)
{
    const int stride = gridDim.x * blockDim.x;
    for (int i = blockIdx.x * blockDim.x + threadIdx.x; i < n4; i += stride) {
        const float4 v = A4[i];
        uint32_t l01, l23;
        const uint32_t h01 = pack_split_hi(v.x, v.y, l01);
        const uint32_t h23 = pack_split_hi(v.z, v.w, l23);
        hi2[i] = make_uint2(h01, h23);
        lo2[i] = make_uint2(l01, l23);
    }
}

// ===========================================================================
// Kernel 0b: W1T_hi/lo[n][k] = bf16-split of W1[k][n]  (tiled transpose)
// ===========================================================================
__global__ __launch_bounds__(256)
void split_w1_kernel(const float* __restrict__ W1,
                     __nv_bfloat16* __restrict__ hi,
                     __nv_bfloat16* __restrict__ lo)
{
    __shared__ float tile[32][33];
    const int bn = blockIdx.x * 32;
    const int bk = blockIdx.y * 32;
    const int tx = threadIdx.x, ty = threadIdx.y;   // 32 x 8
#pragma unroll
    for (int r = ty; r < 32; r += 8)
        tile[r][tx] = W1[(size_t)(bk + r) * Hsz + bn + tx];
    __syncthreads();
#pragma unroll
    for (int r = ty; r < 32; r += 8) {
        const float v = tile[tx][r];      // = W1[bk+tx][bn+r]
        const __nv_bfloat16 h = __float2bfloat16_rn(v);
        const float lf = v - __bfloat162float(h);
        hi[(size_t)(bn + r) * Esz + bk + tx] = h;
        lo[(size_t)(bn + r) * Esz + bk + tx] = __float2bfloat16_rn(lf);
    }
}

// ===========================================================================
// Kernel 1: h = tanh(hidden @ W1 + b1), HMMA bf16 3-product, cp.async
// double-buffered smem + ldmatrix fragments.
// CTA 128x128, 8 warps (warp tile 64x32), KC=32, 24 stages.
// ===========================================================================
#define KC    32
#define NSTG  (Esz / KC)     // 24
#define APAD  40             // bf16 elems per smem row
#define TILE_B (128 * APAD * 2)            // 10240 bytes per tile
#define GEMM_SMEM (8 * TILE_B)             // 81920 bytes

__global__ __launch_bounds__(256, 2)
void gemm1_mma_kernel(const __nv_bfloat16* __restrict__ Ahi_g,
                      const __nv_bfloat16* __restrict__ Alo_g,
                      const __nv_bfloat16* __restrict__ Bhi_g,
                      const __nv_bfloat16* __restrict__ Blo_g,
                      const float* __restrict__ bias,
                      float* __restrict__ Out)
{
    extern __shared__ __nv_bfloat16 smem_g[];
    const uint32_t smem_u32 = (uint32_t)__cvta_generic_to_shared(smem_g);

    const int tid    = threadIdx.x;
    const int wid    = tid >> 5;
    const int lane   = tid & 31;
    const int warp_m = wid >> 2;       // 0..1
    const int warp_n = wid & 3;        // 0..3

    const int m0 = blockIdx.y * 128;
    const int n0 = blockIdx.x * 128;

    const __nv_bfloat16* gsrc[4] = {
        Ahi_g + (size_t)m0 * Esz,
        Alo_g + (size_t)m0 * Esz,
        Bhi_g + (size_t)n0 * Esz,
        Blo_g + (size_t)n0 * Esz
    };

    // cp.async mapping: per tile 512 x 16B chunks; 2 per thread
    const int crow0 = tid >> 2;            // chunk i=0: rows 0..63
    const int ccol  = (tid & 3) * 8;       // elem offset (16B chunks)
    const int crow1 = crow0 + 64;          // chunk i=1

    auto issue_stage = [&](int kt) {
        const int buf = kt & 1;
        const int k0  = kt * KC;
#pragma unroll
        for (int t = 0; t < 4; t++) {
            const uint32_t sbase = smem_u32 + (uint32_t)(t * 2 + buf) * TILE_B;
            cp_async16(sbase + crow0 * (APAD * 2) + ccol * 2,
                       gsrc[t] + (size_t)crow0 * Esz + k0 + ccol);
            cp_async16(sbase + crow1 * (APAD * 2) + ccol * 2,
                       gsrc[t] + (size_t)crow1 * Esz + k0 + ccol);
        }
        CP_ASYNC_COMMIT();
    };

    float acc[4][4][4];
#pragma unroll
    for (int mt = 0; mt < 4; mt++)
#pragma unroll
        for (int nt = 0; nt < 4; nt++)
#pragma unroll
            for (int r = 0; r < 4; r++) acc[mt][nt][r] = 0.0f;

    const int lrow  = (lane & 7) + ((lane >> 3) & 1) * 8;  // row within 16
    const int lcol8 = (lane >> 4) * 8;                     // 0 or 8 (k)

    issue_stage(0);
    issue_stage(1);

    for (int kt = 0; kt < NSTG; ++kt) {
        const int buf = kt & 1;
        if (kt + 1 < NSTG) { CP_ASYNC_WAIT1(); } else { CP_ASYNC_WAIT0(); }
        __syncthreads();

        const uint32_t bAhi = smem_u32 + (uint32_t)(0 * 2 + buf) * TILE_B;
        const uint32_t bAlo = smem_u32 + (uint32_t)(1 * 2 + buf) * TILE_B;
        const uint32_t bBhi = smem_u32 + (uint32_t)(2 * 2 + buf) * TILE_B;
        const uint32_t bBlo = smem_u32 + (uint32_t)(3 * 2 + buf) * TILE_B;

#pragma unroll
        for (int ks = 0; ks < 2; ks++) {
            const int kk = ks * 16;
            const uint32_t coff = (uint32_t)(kk + lcol8) * 2;

            uint32_t ah[4][4], al[4][4], bb[4][2];

#pragma unroll
            for (int mt = 0; mt < 4; mt++) {
                const uint32_t a = bAhi +
                    (uint32_t)(warp_m * 64 + mt * 16 + lrow) * (APAD * 2) + coff;
                ldsm_x4(ah[mt][0], ah[mt][1], ah[mt][2], ah[mt][3], a);
            }
#pragma unroll
            for (int p = 0; p < 2; p++) {
                const uint32_t a = bBhi +
                    (uint32_t)(warp_n * 32 + p * 16 + lrow) * (APAD * 2) + coff;
                ldsm_x4(bb[2 * p][0], bb[2 * p + 1][0],
                        bb[2 * p][1], bb[2 * p + 1][1], a);
            }
            // hi * hi
#pragma unroll
            for (int mt = 0; mt < 4; mt++)
#pragma unroll
                for (int nt = 0; nt < 4; nt++)
                    mma16816(acc[mt][nt], ah[mt], bb[nt]);

            // A-lo fragments, then lo * hi
#pragma unroll
            for (int mt = 0; mt < 4; mt++) {
                const uint32_t a = bAlo +
                    (uint32_t)(warp_m * 64 + mt * 16 + lrow) * (APAD * 2) + coff;
                ldsm_x4(al[mt][0], al[mt][1], al[mt][2], al[mt][3], a);
            }
#pragma unroll
            for (int mt = 0; mt < 4; mt++)
#pragma unroll
                for (int nt = 0; nt < 4; nt++)
                    mma16816(acc[mt][nt], al[mt], bb[nt]);

            // B-lo fragments (reuse bb), then hi * lo
#pragma unroll
            for (int p = 0; p < 2; p++) {
                const uint32_t a = bBlo +
                    (uint32_t)(warp_n * 32 + p * 16 + lrow) * (APAD * 2) + coff;
                ldsm_x4(bb[2 * p][0], bb[2 * p + 1][0],
                        bb[2 * p][1], bb[2 * p + 1][1], a);
            }
#pragma unroll
            for (int mt = 0; mt < 4; mt++)
#pragma unroll
                for (int nt = 0; nt < 4; nt++)
                    mma16816(acc[mt][nt], ah[mt], bb[nt]);
        }
        __syncthreads();
        if (kt + 2 < NSTG) issue_stage(kt + 2);
    }

    // --- Epilogue: bias + tanh ---
    const int r  = lane >> 2;
    const int cp = (lane & 3) * 2;
#pragma unroll
    for (int nt = 0; nt < 4; nt++) {
        const int col = n0 + warp_n * 32 + nt * 8 + cp;
        const float b0 = bias[col];
        const float b1 = bias[col + 1];
#pragma unroll
        for (int mt = 0; mt < 4; mt++) {
            const int row0 = m0 + warp_m * 64 + mt * 16 + r;
            float2 o0, o1;
            o0.x = tanhf(acc[mt][nt][0] + b0);
            o0.y = tanhf(acc[mt][nt][1] + b1);
            o1.x = tanhf(acc[mt][nt][2] + b0);
            o1.y = tanhf(acc[mt][nt][3] + b1);
            *reinterpret_cast<float2*>(Out + (size_t)row0 * Hsz + col)       = o0;
            *reinterpret_cast<float2*>(Out + (size_t)(row0 + 8) * Hsz + col) = o1;
        }
    }
}

// ===========================================================================
// Kernel 2: logits = h @ W2 + b2; softmax C=9; probs; deterministic partials.
// REG-PRESSURE FIX: outer k-chunk loop NOT unrolled (live set ~40 regs vs
// 255 when fully unrolled), __launch_bounds__(256, 6) caps regs at 42 ->
// occupancy 12.5% -> 75%. Kernel becomes DRAM-streaming-bound on h.
// ===========================================================================
__global__ __launch_bounds__(256, 6)
void head_softmax_loss_kernel(const float* __restrict__ h,
                              const float* __restrict__ W2,
                              const float* __restrict__ b2,
                              const int*   __restrict__ labels,
                              const int*   __restrict__ epoch_ptr,
                              float* __restrict__ probs_out)
{
    __shared__ float w2t[Csz][Hsz];    // W2 transposed: [c][k], 27 KB
    __shared__ float sb2[Csz];
    __shared__ float warpsum[8];

    for (int i = threadIdx.x; i < Hsz * Csz; i += blockDim.x) {
        int k = i / Csz, c = i % Csz;
        w2t[c][k] = W2[i];
    }
    if (threadIdx.x < Csz) sb2[threadIdx.x] = b2[threadIdx.x];
    __syncthreads();

    const int epoch = *epoch_ptr;
    const int warp  = threadIdx.x >> 5;
    const int lane  = threadIdx.x & 31;
    const int gwarp = blockIdx.x * 8 + warp;
    const int nwarps = gridDim.x * 8;

    float lsum = 0.0f;

    for (int t = gwarp; t < NTOK; t += nwarps) {
        const float4* hrow = reinterpret_cast<const float4*>(h + (size_t)t * Hsz);
        float acc[Csz];
#pragma unroll
        for (int c = 0; c < Csz; c++) acc[c] = 0.0f;

#pragma unroll 1
        for (int it = 0; it < Hsz / 128; it++) {   // NOT unrolled: keeps regs low
            const int k4 = it * 32 + lane;
            const float4 hv = hrow[k4];
#pragma unroll
            for (int c = 0; c < Csz; c++) {
                const float4 wv = reinterpret_cast<const float4*>(&w2t[c][0])[k4];
                acc[c] += hv.x * wv.x + hv.y * wv.y + hv.z * wv.z + hv.w * wv.w;
            }
        }

#pragma unroll
        for (int c = 0; c < Csz; c++) {
            float v = acc[c];
#pragma unroll
            for (int o = 16; o > 0; o >>= 1)
                v += __shfl_xor_sync(0xffffffffu, v, o);
            acc[c] = v + sb2[c];
        }

        float m = acc[0];
#pragma unroll
        for (int c = 1; c < Csz; c++) m = fmaxf(m, acc[c]);
        float e[Csz];
        float s = 0.0f;
#pragma unroll
        for (int c = 0; c < Csz; c++) { e[c] = expf(acc[c] - m); s += e[c]; }
        const float inv_s = 1.0f / s;

        if (lane < Csz)
            probs_out[(size_t)t * Csz + lane] = e[lane] * inv_s;

        if (lane == 0) {
            const int lbl = labels[t];
            if (lbl != IGNORE_LBL) {
                const float p = e[lbl] * inv_s;
                const float w = (epoch <= 2) ? 1.0f : (p > TAU_F ? 1.0f : 0.0f);
                if (w != 0.0f)
                    lsum += (1.0f - powf(p, QGCE_F)) * (1.0f / QGCE_F);
            }
        }
    }

    if (lane == 0) warpsum[warp] = lsum;
    __syncthreads();
    if (threadIdx.x == 0) {
        float s = 0.0f;
#pragma unroll
        for (int w = 0; w < 8; w++) s += warpsum[w];
        g_partials[blockIdx.x] = s;
    }
}

// ===========================================================================
// Kernel 3: deterministic (fixed-order tree) final loss reduction
// ===========================================================================
__global__ __launch_bounds__(256)
void finalize_loss_kernel(float* __restrict__ loss_out)
{
    __shared__ float s[256];
    const int t = threadIdx.x;
    s[t] = g_partials[t] + g_partials[t + 256];
    __syncthreads();
#pragma unroll
    for (int o = 128; o > 0; o >>= 1) {
        if (t < o) s[t] += s[t + o];
        __syncthreads();
    }
    if (t == 0) *loss_out = s[0];
}

// ===========================================================================
// Launch. Inputs: hidden, W1, b1, W2, b2, labels, epoch.
// Output: probs [B*S*C] fp32, then loss [1] fp32.
// ===========================================================================
extern "C" void kernel_launch(void* const* d_in, const int* in_sizes, int n_in,
                              void* d_out, int out_size)
{
    const float* hidden = (const float*)d_in[0];
    const float* W1     = (const float*)d_in[1];
    const float* b1     = (const float*)d_in[2];
    const float* W2     = (const float*)d_in[3];
    const float* b2     = (const float*)d_in[4];
    const int*   labels = (const int*)  d_in[5];
    const int*   epoch  = (const int*)  d_in[6];

    float* out = (float*)d_out;
    const int PROBS_N = NTOK * Csz;   // 294912

    float* probs_dst = out;
    float* loss_dst  = nullptr;
    if (out_size >= PROBS_N + 1) {
        loss_dst = out + PROBS_N;
    } else if (out_size < PROBS_N) {
        void* sink = nullptr;
        cudaGetSymbolAddress(&sink, g_probs_sink);
        probs_dst = (float*)sink;
        if (out_size >= 1) loss_dst = out;
    }

    float* hbuf = nullptr;
    cudaGetSymbolAddress((void**)&hbuf, g_h);
    __nv_bfloat16 *a_hi = nullptr, *a_lo = nullptr, *w1t_hi = nullptr, *w1t_lo = nullptr;
    cudaGetSymbolAddress((void**)&a_hi, g_A_hi);
    cudaGetSymbolAddress((void**)&a_lo, g_A_lo);
    cudaGetSymbolAddress((void**)&w1t_hi, g_W1T_hi);
    cudaGetSymbolAddress((void**)&w1t_lo, g_W1T_lo);

    // 0) split A and W1 to bf16 hi/lo
    const int n4 = NTOK * Esz / 4;    // 6291456 float4s
    split_a_kernel<<<6144, 256>>>((const float4*)hidden,
                                  (uint2*)a_hi, (uint2*)a_lo, n4);
    split_w1_kernel<<<dim3(Hsz / 32, Esz / 32), dim3(32, 8)>>>(W1, w1t_hi, w1t_lo);

    // 1) h = tanh(hidden @ W1 + b1): cp.async + ldmatrix + HMMA 3-product
    cudaFuncSetAttribute(gemm1_mma_kernel,
                         cudaFuncAttributeMaxDynamicSharedMemorySize, GEMM_SMEM);
    dim3 g1(Hsz / 128, NTOK / 128);   // (6, 256)
    gemm1_mma_kernel<<<g1, 256, GEMM_SMEM>>>(a_hi, a_lo, w1t_hi, w1t_lo, b1, hbuf);

    // 2) head + softmax + probs + loss partials
    head_softmax_loss_kernel<<<LOSS_BLOCKS, 256>>>(hbuf, W2, b2, labels,
                                                   epoch, probs_dst);

    // 3) deterministic loss finalize
    if (loss_dst != nullptr)
        finalize_loss_kernel<<<1, 256>>>(loss_dst);
}

// round 16
// speedup vs baseline: 2.1812x; 1.0209x over previous
#include <cuda_runtime.h>
#include <cuda_bf16.h>
#include <math.h>
#include <stdint.h>

// Problem shapes (fixed by reference)
#define Bsz   64
#define Ssz   512
#define Esz   768
#define Hsz   768
#define Csz   9
#define NTOK  (Bsz * Ssz)          // 32768 tokens
#define IGNORE_LBL (-100)
#define TAU_F  0.7f
#define QGCE_F 0.7f

// Scratch buffers (static device memory; no runtime alloc)
__device__ float g_h[(size_t)NTOK * Hsz];                  // 96 MB
__device__ __nv_bfloat16 g_W1T_hi[(size_t)Hsz * Esz];
__device__ __nv_bfloat16 g_W1T_lo[(size_t)Hsz * Esz];
__device__ float g_probs_sink[(size_t)NTOK * Csz];
#define LOSS_BLOCKS 1024
__device__ float g_partials[LOSS_BLOCKS];

// ===========================================================================
// Common helpers
// ===========================================================================
__device__ __forceinline__ uint32_t pack_split_hi(float x, float y,
                                                  uint32_t& lo_out)
{
    const __nv_bfloat16 hx = __float2bfloat16_rn(x);
    const __nv_bfloat16 hy = __float2bfloat16_rn(y);
    const __nv_bfloat16 lx = __float2bfloat16_rn(x - __bfloat162float(hx));
    const __nv_bfloat16 ly = __float2bfloat16_rn(y - __bfloat162float(hy));
    __nv_bfloat162 hp; hp.x = hx; hp.y = hy;
    __nv_bfloat162 lp; lp.x = lx; lp.y = ly;
    lo_out = *reinterpret_cast<uint32_t*>(&lp);
    return *reinterpret_cast<uint32_t*>(&hp);
}

__device__ __forceinline__ void mma16816(float* c, const uint32_t* a,
                                         const uint32_t* b)
{
    asm volatile(
        "mma.sync.aligned.m16n8k16.row.col.f32.bf16.bf16.f32 "
        "{%0,%1,%2,%3}, {%4,%5,%6,%7}, {%8,%9}, {%0,%1,%2,%3};"
        : "+f"(c[0]), "+f"(c[1]), "+f"(c[2]), "+f"(c[3])
        : "r"(a[0]), "r"(a[1]), "r"(a[2]), "r"(a[3]),
          "r"(b[0]), "r"(b[1]));
}

__device__ __forceinline__ void ldsm_x4(uint32_t& r0, uint32_t& r1,
                                        uint32_t& r2, uint32_t& r3,
                                        uint32_t saddr)
{
    asm volatile("ldmatrix.sync.aligned.m8n8.x4.shared.b16 {%0,%1,%2,%3}, [%4];"
                 : "=r"(r0), "=r"(r1), "=r"(r2), "=r"(r3) : "r"(saddr));
}

__device__ __forceinline__ void cp_async16(uint32_t dst, const void* src)
{
    asm volatile("cp.async.cg.shared.global [%0], [%1], 16;"
                 :: "r"(dst), "l"(src));
}
#define CP_ASYNC_COMMIT() asm volatile("cp.async.commit_group;" ::: "memory")
#define CP_ASYNC_WAIT1()  asm volatile("cp.async.wait_group 1;" ::: "memory")
#define CP_ASYNC_WAIT0()  asm volatile("cp.async.wait_group 0;" ::: "memory")

// ===========================================================================
// Kernel 0: W1T_hi/lo[n][k] = bf16-split of W1[k][n]  (tiled transpose)
// ===========================================================================
__global__ __launch_bounds__(256)
void split_w1_kernel(const float* __restrict__ W1,
                     __nv_bfloat16* __restrict__ hi,
                     __nv_bfloat16* __restrict__ lo)
{
    __shared__ float tile[32][33];
    const int bn = blockIdx.x * 32;
    const int bk = blockIdx.y * 32;
    const int tx = threadIdx.x, ty = threadIdx.y;   // 32 x 8
#pragma unroll
    for (int r = ty; r < 32; r += 8)
        tile[r][tx] = W1[(size_t)(bk + r) * Hsz + bn + tx];
    __syncthreads();
#pragma unroll
    for (int r = ty; r < 32; r += 8) {
        const float v = tile[tx][r];      // = W1[bk+tx][bn+r]
        const __nv_bfloat16 h = __float2bfloat16_rn(v);
        const float lf = v - __bfloat162float(h);
        hi[(size_t)(bn + r) * Esz + bk + tx] = h;
        lo[(size_t)(bn + r) * Esz + bk + tx] = __float2bfloat16_rn(lf);
    }
}

// ===========================================================================
// Kernel 1: h = tanh(hidden @ W1 + b1), HMMA bf16 3-product.
// A (fp32) loaded + bf16 hi/lo split in registers, STS'd directly (no
// separate split_a global pass). B (pre-split bf16) via cp.async
// double-buffered. ldmatrix fragments.
// RACE FIX vs R15: issue_B(kt+2) is AFTER the trailing __syncthreads() —
// B(kt+2) targets the same double-buffer slot the current stage reads, so
// its cp.async writes must not start until all B(kt) reads passed the
// barrier (this was the R15 rel_err=0.65 bug).
// CTA 128x128, 8 warps (warp tile 64x32), KC=32, 24 stages.
// ===========================================================================
#define KC    32
#define NSTG  (Esz / KC)     // 24
#define APAD  40             // bf16 elems per smem row (80 B)
#define TILE_B (128 * APAD * 2)            // 10240 bytes per tile
#define GEMM_SMEM (8 * TILE_B)             // 81920 bytes

__global__ __launch_bounds__(256, 2)
void gemm1_mma_kernel(const float* __restrict__ A,
                      const __nv_bfloat16* __restrict__ Bhi_g,
                      const __nv_bfloat16* __restrict__ Blo_g,
                      const float* __restrict__ bias,
                      float* __restrict__ Out)
{
    extern __shared__ __nv_bfloat16 smem_g[];
    const uint32_t smem_u32 = (uint32_t)__cvta_generic_to_shared(smem_g);

    const int tid    = threadIdx.x;
    const int wid    = tid >> 5;
    const int lane   = tid & 31;
    const int warp_m = wid >> 2;       // 0..1
    const int warp_n = wid & 3;        // 0..3

    const int m0 = blockIdx.y * 128;
    const int n0 = blockIdx.x * 128;

    const float* Ab = A + (size_t)m0 * Esz;
    const __nv_bfloat16* gB[2] = {
        Bhi_g + (size_t)n0 * Esz,
        Blo_g + (size_t)n0 * Esz
    };

    const int acol = (tid & 7) * 4;        // fp32 elem offset within KC

    auto issue_B = [&](int kt) {
        const int buf = kt & 1;
        const int k0  = kt * KC;
#pragma unroll
        for (int t = 0; t < 2; t++) {
            const uint32_t sbase = smem_u32 + (uint32_t)((2 + t) * 2 + buf) * TILE_B;
#pragma unroll
            for (int i = 0; i < 2; i++) {
                const int u   = i * 256 + tid;
                const int row = u >> 2;
                const int c   = (u & 3) * 8;
                cp_async16(sbase + row * (APAD * 2) + c * 2,
                           gB[t] + (size_t)row * Esz + k0 + c);
            }
        }
        CP_ASYNC_COMMIT();
    };

    float acc[4][4][4];
#pragma unroll
    for (int mt = 0; mt < 4; mt++)
#pragma unroll
        for (int nt = 0; nt < 4; nt++)
#pragma unroll
            for (int r = 0; r < 4; r++) acc[mt][nt][r] = 0.0f;

    const int lrow  = (lane & 7) + ((lane >> 3) & 1) * 8;  // row within 16
    const int lcol8 = (lane >> 4) * 8;                     // 0 or 8 (k)

    // Prologue: A(0) into registers; B(0), B(1) via cp.async
    float4 pa[4];
#pragma unroll
    for (int i = 0; i < 4; i++) {
        const int row = (i * 256 + tid) >> 3;
        pa[i] = *reinterpret_cast<const float4*>(Ab + (size_t)row * Esz + acol);
    }
    issue_B(0);
    issue_B(1);

    for (int kt = 0; kt < NSTG; ++kt) {
        const int buf = kt & 1;
        if (kt + 1 < NSTG) { CP_ASYNC_WAIT1(); } else { CP_ASYNC_WAIT0(); }

        // Stage A(kt): convert fp32 regs -> bf16 hi/lo, STS
        {
            const uint32_t bAhi = smem_u32 + (uint32_t)(0 * 2 + buf) * TILE_B;
            const uint32_t bAlo = smem_u32 + (uint32_t)(1 * 2 + buf) * TILE_B;
#pragma unroll
            for (int i = 0; i < 4; i++) {
                const int row = (i * 256 + tid) >> 3;
                uint32_t l01, l23;
                const uint32_t h01 = pack_split_hi(pa[i].x, pa[i].y, l01);
                const uint32_t h23 = pack_split_hi(pa[i].z, pa[i].w, l23);
                const uint32_t off = (uint32_t)row * (APAD * 2) + acol * 2;
                asm volatile("st.shared.v2.b32 [%0], {%1, %2};"
                             :: "r"(bAhi + off), "r"(h01), "r"(h23) : "memory");
                asm volatile("st.shared.v2.b32 [%0], {%1, %2};"
                             :: "r"(bAlo + off), "r"(l01), "r"(l23) : "memory");
            }
        }
        __syncthreads();

        // Prefetch A(kt+1) into registers (overlaps compute below)
        if (kt + 1 < NSTG) {
            const int k0n = (kt + 1) * KC;
#pragma unroll
            for (int i = 0; i < 4; i++) {
                const int row = (i * 256 + tid) >> 3;
                pa[i] = *reinterpret_cast<const float4*>(
                    Ab + (size_t)row * Esz + k0n + acol);
            }
        }

        const uint32_t bAhi = smem_u32 + (uint32_t)(0 * 2 + buf) * TILE_B;
        const uint32_t bAlo = smem_u32 + (uint32_t)(1 * 2 + buf) * TILE_B;
        const uint32_t bBhi = smem_u32 + (uint32_t)(2 * 2 + buf) * TILE_B;
        const uint32_t bBlo = smem_u32 + (uint32_t)(3 * 2 + buf) * TILE_B;

#pragma unroll
        for (int ks = 0; ks < 2; ks++) {
            const int kk = ks * 16;
            const uint32_t coff = (uint32_t)(kk + lcol8) * 2;

            uint32_t ah[4][4], al[4][4], bb[4][2];

#pragma unroll
            for (int mt = 0; mt < 4; mt++) {
                const uint32_t a = bAhi +
                    (uint32_t)(warp_m * 64 + mt * 16 + lrow) * (APAD * 2) + coff;
                ldsm_x4(ah[mt][0], ah[mt][1], ah[mt][2], ah[mt][3], a);
            }
#pragma unroll
            for (int p = 0; p < 2; p++) {
                const uint32_t a = bBhi +
                    (uint32_t)(warp_n * 32 + p * 16 + lrow) * (APAD * 2) + coff;
                ldsm_x4(bb[2 * p][0], bb[2 * p + 1][0],
                        bb[2 * p][1], bb[2 * p + 1][1], a);
            }
            // hi * hi
#pragma unroll
            for (int mt = 0; mt < 4; mt++)
#pragma unroll
                for (int nt = 0; nt < 4; nt++)
                    mma16816(acc[mt][nt], ah[mt], bb[nt]);

            // A-lo fragments, then lo * hi
#pragma unroll
            for (int mt = 0; mt < 4; mt++) {
                const uint32_t a = bAlo +
                    (uint32_t)(warp_m * 64 + mt * 16 + lrow) * (APAD * 2) + coff;
                ldsm_x4(al[mt][0], al[mt][1], al[mt][2], al[mt][3], a);
            }
#pragma unroll
            for (int mt = 0; mt < 4; mt++)
#pragma unroll
                for (int nt = 0; nt < 4; nt++)
                    mma16816(acc[mt][nt], al[mt], bb[nt]);

            // B-lo fragments (reuse bb), then hi * lo
#pragma unroll
            for (int p = 0; p < 2; p++) {
                const uint32_t a = bBlo +
                    (uint32_t)(warp_n * 32 + p * 16 + lrow) * (APAD * 2) + coff;
                ldsm_x4(bb[2 * p][0], bb[2 * p + 1][0],
                        bb[2 * p][1], bb[2 * p + 1][1], a);
            }
#pragma unroll
            for (int mt = 0; mt < 4; mt++)
#pragma unroll
                for (int nt = 0; nt < 4; nt++)
                    mma16816(acc[mt][nt], ah[mt], bb[nt]);
        }
        __syncthreads();
        // SAFE POINT: all reads of B(kt) from buffer `buf` completed above.
        if (kt + 2 < NSTG) issue_B(kt + 2);
    }

    // --- Epilogue: bias + tanh ---
    const int r  = lane >> 2;
    const int cp = (lane & 3) * 2;
#pragma unroll
    for (int nt = 0; nt < 4; nt++) {
        const int col = n0 + warp_n * 32 + nt * 8 + cp;
        const float b0 = bias[col];
        const float b1 = bias[col + 1];
#pragma unroll
        for (int mt = 0; mt < 4; mt++) {
            const int row0 = m0 + warp_m * 64 + mt * 16 + r;
            float2 o0, o1;
            o0.x = tanhf(acc[mt][nt][0] + b0);
            o0.y = tanhf(acc[mt][nt][1] + b1);
            o1.x = tanhf(acc[mt][nt][2] + b0);
            o1.y = tanhf(acc[mt][nt][3] + b1);
            *reinterpret_cast<float2*>(Out + (size_t)row0 * Hsz + col)       = o0;
            *reinterpret_cast<float2*>(Out + (size_t)(row0 + 8) * Hsz + col) = o1;
        }
    }
}

// ===========================================================================
// Kernel 2: logits = h @ W2 + b2; softmax C=9; probs; deterministic partials.
// 1024 blocks, regs capped via (256,6): DRAM-streaming-bound on h.
// ===========================================================================
__global__ __launch_bounds__(256, 6)
void head_softmax_loss_kernel(const float* __restrict__ h,
                              const float* __restrict__ W2,
                              const float* __restrict__ b2,
                              const int*   __restrict__ labels,
                              const int*   __restrict__ epoch_ptr,
                              float* __restrict__ probs_out)
{
    __shared__ float w2t[Csz][Hsz];    // W2 transposed: [c][k], 27 KB
    __shared__ float sb2[Csz];
    __shared__ float warpsum[8];

    for (int i = threadIdx.x; i < Hsz * Csz; i += blockDim.x) {
        int k = i / Csz, c = i % Csz;
        w2t[c][k] = W2[i];
    }
    if (threadIdx.x < Csz) sb2[threadIdx.x] = b2[threadIdx.x];
    __syncthreads();

    const int epoch = *epoch_ptr;
    const int warp  = threadIdx.x >> 5;
    const int lane  = threadIdx.x & 31;
    const int gwarp = blockIdx.x * 8 + warp;
    const int nwarps = gridDim.x * 8;

    float lsum = 0.0f;

    for (int t = gwarp; t < NTOK; t += nwarps) {
        const float4* hrow = reinterpret_cast<const float4*>(h + (size_t)t * Hsz);
        float acc[Csz];
#pragma unroll
        for (int c = 0; c < Csz; c++) acc[c] = 0.0f;

#pragma unroll 1
        for (int it = 0; it < Hsz / 128; it++) {   // NOT unrolled: keeps regs low
            const int k4 = it * 32 + lane;
            const float4 hv = hrow[k4];
#pragma unroll
            for (int c = 0; c < Csz; c++) {
                const float4 wv = reinterpret_cast<const float4*>(&w2t[c][0])[k4];
                acc[c] += hv.x * wv.x + hv.y * wv.y + hv.z * wv.z + hv.w * wv.w;
            }
        }

#pragma unroll
        for (int c = 0; c < Csz; c++) {
            float v = acc[c];
#pragma unroll
            for (int o = 16; o > 0; o >>= 1)
                v += __shfl_xor_sync(0xffffffffu, v, o);
            acc[c] = v + sb2[c];
        }

        float m = acc[0];
#pragma unroll
        for (int c = 1; c < Csz; c++) m = fmaxf(m, acc[c]);
        float e[Csz];
        float s = 0.0f;
#pragma unroll
        for (int c = 0; c < Csz; c++) { e[c] = expf(acc[c] - m); s += e[c]; }
        const float inv_s = 1.0f / s;

        if (lane < Csz)
            probs_out[(size_t)t * Csz + lane] = e[lane] * inv_s;

        if (lane == 0) {
            const int lbl = labels[t];
            if (lbl != IGNORE_LBL) {
                const float p = e[lbl] * inv_s;
                const float w = (epoch <= 2) ? 1.0f : (p > TAU_F ? 1.0f : 0.0f);
                if (w != 0.0f)
                    lsum += (1.0f - powf(p, QGCE_F)) * (1.0f / QGCE_F);
            }
        }
    }

    if (lane == 0) warpsum[warp] = lsum;
    __syncthreads();
    if (threadIdx.x == 0) {
        float s = 0.0f;
#pragma unroll
        for (int w = 0; w < 8; w++) s += warpsum[w];
        g_partials[blockIdx.x] = s;
    }
}

// ===========================================================================
// Kernel 3: deterministic (fixed-order tree) final loss reduction (1024)
// ===========================================================================
__global__ __launch_bounds__(256)
void finalize_loss_kernel(float* __restrict__ loss_out)
{
    __shared__ float s[256];
    const int t = threadIdx.x;
    s[t] = (g_partials[t]       + g_partials[t + 256]) +
           (g_partials[t + 512] + g_partials[t + 768]);
    __syncthreads();
#pragma unroll
    for (int o = 128; o > 0; o >>= 1) {
        if (t < o) s[t] += s[t + o];
        __syncthreads();
    }
    if (t == 0) *loss_out = s[0];
}

// ===========================================================================
// Launch. Inputs: hidden, W1, b1, W2, b2, labels, epoch.
// Output: probs [B*S*C] fp32, then loss [1] fp32.
// ===========================================================================
extern "C" void kernel_launch(void* const* d_in, const int* in_sizes, int n_in,
                              void* d_out, int out_size)
{
    const float* hidden = (const float*)d_in[0];
    const float* W1     = (const float*)d_in[1];
    const float* b1     = (const float*)d_in[2];
    const float* W2     = (const float*)d_in[3];
    const float* b2     = (const float*)d_in[4];
    const int*   labels = (const int*)  d_in[5];
    const int*   epoch  = (const int*)  d_in[6];

    float* out = (float*)d_out;
    const int PROBS_N = NTOK * Csz;   // 294912

    float* probs_dst = out;
    float* loss_dst  = nullptr;
    if (out_size >= PROBS_N + 1) {
        loss_dst = out + PROBS_N;
    } else if (out_size < PROBS_N) {
        void* sink = nullptr;
        cudaGetSymbolAddress(&sink, g_probs_sink);
        probs_dst = (float*)sink;
        if (out_size >= 1) loss_dst = out;
    }

    float* hbuf = nullptr;
    cudaGetSymbolAddress((void**)&hbuf, g_h);
    __nv_bfloat16 *w1t_hi = nullptr, *w1t_lo = nullptr;
    cudaGetSymbolAddress((void**)&w1t_hi, g_W1T_hi);
    cudaGetSymbolAddress((void**)&w1t_lo, g_W1T_lo);

    // 0) transpose + bf16-split W1 (A split is fused into the GEMM)
    split_w1_kernel<<<dim3(Hsz / 32, Esz / 32), dim3(32, 8)>>>(W1, w1t_hi, w1t_lo);

    // 1) h = tanh(hidden @ W1 + b1): fused A-split + cp.async B + HMMA
    cudaFuncSetAttribute(gemm1_mma_kernel,
                         cudaFuncAttributeMaxDynamicSharedMemorySize, GEMM_SMEM);
    dim3 g1(Hsz / 128, NTOK / 128);   // (6, 256)
    gemm1_mma_kernel<<<g1, 256, GEMM_SMEM>>>(hidden, w1t_hi, w1t_lo, b1, hbuf);

    // 2) head + softmax + probs + loss partials
    head_softmax_loss_kernel<<<LOSS_BLOCKS, 256>>>(hbuf, W2, b2, labels,
                                                   epoch, probs_dst);

    // 3) deterministic loss finalize
    if (loss_dst != nullptr)
        finalize_loss_kernel<<<1, 256>>>(loss_dst);
}

// round 17
// speedup vs baseline: 2.2738x; 1.0425x over previous
#include <cuda_runtime.h>
#include <cuda_bf16.h>
#include <math.h>
#include <stdint.h>

// Problem shapes (fixed by reference)
#define Bsz   64
#define Ssz   512
#define Esz   768
#define Hsz   768
#define Csz   9
#define NTOK  (Bsz * Ssz)          // 32768 tokens
#define IGNORE_LBL (-100)
#define TAU_F  0.7f
#define QGCE_F 0.7f
#define NBLK  (Hsz / 128)          // 6 column blocks

// Scratch buffers (static device memory; no runtime alloc)
__device__ __nv_bfloat16 g_A_hi[(size_t)NTOK * Esz];       // 48 MB
__device__ __nv_bfloat16 g_A_lo[(size_t)NTOK * Esz];       // 48 MB
__device__ __nv_bfloat16 g_W1T_hi[(size_t)Hsz * Esz];
__device__ __nv_bfloat16 g_W1T_lo[(size_t)Hsz * Esz];
// Partial logits: one slice per N-column-block; each slot written by exactly
// one CTA -> deterministic, no atomics. 6*32768*9*4B = 7.08 MB.
__device__ float g_part[(size_t)NBLK * NTOK * Csz];
__device__ float g_probs_sink[(size_t)NTOK * Csz];
#define LOSS_BLOCKS 128
__device__ float g_partials[LOSS_BLOCKS];

// ===========================================================================
// Common helpers
// ===========================================================================
__device__ __forceinline__ uint32_t pack_split_hi(float x, float y,
                                                  uint32_t& lo_out)
{
    const __nv_bfloat16 hx = __float2bfloat16_rn(x);
    const __nv_bfloat16 hy = __float2bfloat16_rn(y);
    const __nv_bfloat16 lx = __float2bfloat16_rn(x - __bfloat162float(hx));
    const __nv_bfloat16 ly = __float2bfloat16_rn(y - __bfloat162float(hy));
    __nv_bfloat162 hp; hp.x = hx; hp.y = hy;
    __nv_bfloat162 lp; lp.x = lx; lp.y = ly;
    lo_out = *reinterpret_cast<uint32_t*>(&lp);
    return *reinterpret_cast<uint32_t*>(&hp);
}

__device__ __forceinline__ void mma16816(float* c, const uint32_t* a,
                                         const uint32_t* b)
{
    asm volatile(
        "mma.sync.aligned.m16n8k16.row.col.f32.bf16.bf16.f32 "
        "{%0,%1,%2,%3}, {%4,%5,%6,%7}, {%8,%9}, {%0,%1,%2,%3};"
        : "+f"(c[0]), "+f"(c[1]), "+f"(c[2]), "+f"(c[3])
        : "r"(a[0]), "r"(a[1]), "r"(a[2]), "r"(a[3]),
          "r"(b[0]), "r"(b[1]));
}

__device__ __forceinline__ void ldsm_x4(uint32_t& r0, uint32_t& r1,
                                        uint32_t& r2, uint32_t& r3,
                                        uint32_t saddr)
{
    asm volatile("ldmatrix.sync.aligned.m8n8.x4.shared.b16 {%0,%1,%2,%3}, [%4];"
                 : "=r"(r0), "=r"(r1), "=r"(r2), "=r"(r3) : "r"(saddr));
}

__device__ __forceinline__ void cp_async16(uint32_t dst, const void* src)
{
    asm volatile("cp.async.cg.shared.global [%0], [%1], 16;"
                 :: "r"(dst), "l"(src));
}
#define CP_ASYNC_COMMIT() asm volatile("cp.async.commit_group;" ::: "memory")
#define CP_ASYNC_WAIT1()  asm volatile("cp.async.wait_group 1;" ::: "memory")
#define CP_ASYNC_WAIT0()  asm volatile("cp.async.wait_group 0;" ::: "memory")

// ===========================================================================
// Kernel 0a: elementwise bf16-split of A (hidden): hi + lo
// ===========================================================================
__global__ __launch_bounds__(256)
void split_a_kernel(const float4* __restrict__ A4,
                    uint2* __restrict__ hi2,
                    uint2* __restrict__ lo2, int n4)
{
    const int stride = gridDim.x * blockDim.x;
    for (int i = blockIdx.x * blockDim.x + threadIdx.x; i < n4; i += stride) {
        const float4 v = A4[i];
        uint32_t l01, l23;
        const uint32_t h01 = pack_split_hi(v.x, v.y, l01);
        const uint32_t h23 = pack_split_hi(v.z, v.w, l23);
        hi2[i] = make_uint2(h01, h23);
        lo2[i] = make_uint2(l01, l23);
    }
}

// ===========================================================================
// Kernel 0b: W1T_hi/lo[n][k] = bf16-split of W1[k][n]  (tiled transpose)
// ===========================================================================
__global__ __launch_bounds__(256)
void split_w1_kernel(const float* __restrict__ W1,
                     __nv_bfloat16* __restrict__ hi,
                     __nv_bfloat16* __restrict__ lo)
{
    __shared__ float tile[32][33];
    const int bn = blockIdx.x * 32;
    const int bk = blockIdx.y * 32;
    const int tx = threadIdx.x, ty = threadIdx.y;   // 32 x 8
#pragma unroll
    for (int r = ty; r < 32; r += 8)
        tile[r][tx] = W1[(size_t)(bk + r) * Hsz + bn + tx];
    __syncthreads();
#pragma unroll
    for (int r = ty; r < 32; r += 8) {
        const float v = tile[tx][r];      // = W1[bk+tx][bn+r]
        const __nv_bfloat16 h = __float2bfloat16_rn(v);
        const float lf = v - __bfloat162float(h);
        hi[(size_t)(bn + r) * Esz + bk + tx] = h;
        lo[(size_t)(bn + r) * Esz + bk + tx] = __float2bfloat16_rn(lf);
    }
}

// ===========================================================================
// Kernel 1: fused GEMM1 + tanh + partial GEMM2.
// Mainloop identical to the twice-passed R13/R14 version (4 operand tiles via
// cp.async double-buffered, ldmatrix fragments, issue after trailing barrier).
// Epilogue: h = tanh(acc + b1) stays in registers; partial logits over this
// CTA's 128 h-columns are reduced (fixed-order shfl + fixed-order smem
// combine) and written to g_part[bn] — h is never materialized in global.
// ===========================================================================
#define KC    32
#define NSTG  (Esz / KC)     // 24
#define APAD  40             // bf16 elems per smem row (80 B)
#define TILE_B (128 * APAD * 2)            // 10240 bytes per tile
#define GEMM_SMEM (8 * TILE_B)             // 81920 bytes

__global__ __launch_bounds__(256, 2)
void gemm1_mma_kernel(const __nv_bfloat16* __restrict__ Ahi_g,
                      const __nv_bfloat16* __restrict__ Alo_g,
                      const __nv_bfloat16* __restrict__ Bhi_g,
                      const __nv_bfloat16* __restrict__ Blo_g,
                      const float* __restrict__ bias,
                      const float* __restrict__ W2,
                      float* __restrict__ PartOut)
{
    extern __shared__ __nv_bfloat16 smem_g[];
    const uint32_t smem_u32 = (uint32_t)__cvta_generic_to_shared(smem_g);

    const int tid    = threadIdx.x;
    const int wid    = tid >> 5;
    const int lane   = tid & 31;
    const int warp_m = wid >> 2;       // 0..1
    const int warp_n = wid & 3;        // 0..3

    const int m0 = blockIdx.y * 128;
    const int n0 = blockIdx.x * 128;
    const int bn = blockIdx.x;         // column-block id for partials

    const __nv_bfloat16* gsrc[4] = {
        Ahi_g + (size_t)m0 * Esz,
        Alo_g + (size_t)m0 * Esz,
        Bhi_g + (size_t)n0 * Esz,
        Blo_g + (size_t)n0 * Esz
    };

    const int crow0 = tid >> 2;            // chunk i=0: rows 0..63
    const int ccol  = (tid & 3) * 8;       // elem offset (16B chunks)
    const int crow1 = crow0 + 64;          // chunk i=1

    auto issue_stage = [&](int kt) {
        const int buf = kt & 1;
        const int k0  = kt * KC;
#pragma unroll
        for (int t = 0; t < 4; t++) {
            const uint32_t sbase = smem_u32 + (uint32_t)(t * 2 + buf) * TILE_B;
            cp_async16(sbase + crow0 * (APAD * 2) + ccol * 2,
                       gsrc[t] + (size_t)crow0 * Esz + k0 + ccol);
            cp_async16(sbase + crow1 * (APAD * 2) + ccol * 2,
                       gsrc[t] + (size_t)crow1 * Esz + k0 + ccol);
        }
        CP_ASYNC_COMMIT();
    };

    float acc[4][4][4];
#pragma unroll
    for (int mt = 0; mt < 4; mt++)
#pragma unroll
        for (int nt = 0; nt < 4; nt++)
#pragma unroll
            for (int r = 0; r < 4; r++) acc[mt][nt][r] = 0.0f;

    const int lrow  = (lane & 7) + ((lane >> 3) & 1) * 8;  // row within 16
    const int lcol8 = (lane >> 4) * 8;                     // 0 or 8 (k)

    issue_stage(0);
    issue_stage(1);

    for (int kt = 0; kt < NSTG; ++kt) {
        const int buf = kt & 1;
        if (kt + 1 < NSTG) { CP_ASYNC_WAIT1(); } else { CP_ASYNC_WAIT0(); }
        __syncthreads();

        const uint32_t bAhi = smem_u32 + (uint32_t)(0 * 2 + buf) * TILE_B;
        const uint32_t bAlo = smem_u32 + (uint32_t)(1 * 2 + buf) * TILE_B;
        const uint32_t bBhi = smem_u32 + (uint32_t)(2 * 2 + buf) * TILE_B;
        const uint32_t bBlo = smem_u32 + (uint32_t)(3 * 2 + buf) * TILE_B;

#pragma unroll
        for (int ks = 0; ks < 2; ks++) {
            const int kk = ks * 16;
            const uint32_t coff = (uint32_t)(kk + lcol8) * 2;

            uint32_t ah[4][4], al[4][4], bb[4][2];

#pragma unroll
            for (int mt = 0; mt < 4; mt++) {
                const uint32_t a = bAhi +
                    (uint32_t)(warp_m * 64 + mt * 16 + lrow) * (APAD * 2) + coff;
                ldsm_x4(ah[mt][0], ah[mt][1], ah[mt][2], ah[mt][3], a);
            }
#pragma unroll
            for (int p = 0; p < 2; p++) {
                const uint32_t a = bBhi +
                    (uint32_t)(warp_n * 32 + p * 16 + lrow) * (APAD * 2) + coff;
                ldsm_x4(bb[2 * p][0], bb[2 * p + 1][0],
                        bb[2 * p][1], bb[2 * p + 1][1], a);
            }
            // hi * hi
#pragma unroll
            for (int mt = 0; mt < 4; mt++)
#pragma unroll
                for (int nt = 0; nt < 4; nt++)
                    mma16816(acc[mt][nt], ah[mt], bb[nt]);

            // A-lo fragments, then lo * hi
#pragma unroll
            for (int mt = 0; mt < 4; mt++) {
                const uint32_t a = bAlo +
                    (uint32_t)(warp_m * 64 + mt * 16 + lrow) * (APAD * 2) + coff;
                ldsm_x4(al[mt][0], al[mt][1], al[mt][2], al[mt][3], a);
            }
#pragma unroll
            for (int mt = 0; mt < 4; mt++)
#pragma unroll
                for (int nt = 0; nt < 4; nt++)
                    mma16816(acc[mt][nt], al[mt], bb[nt]);

            // B-lo fragments (reuse bb), then hi * lo
#pragma unroll
            for (int p = 0; p < 2; p++) {
                const uint32_t a = bBlo +
                    (uint32_t)(warp_n * 32 + p * 16 + lrow) * (APAD * 2) + coff;
                ldsm_x4(bb[2 * p][0], bb[2 * p + 1][0],
                        bb[2 * p][1], bb[2 * p + 1][1], a);
            }
#pragma unroll
            for (int mt = 0; mt < 4; mt++)
#pragma unroll
                for (int nt = 0; nt < 4; nt++)
                    mma16816(acc[mt][nt], ah[mt], bb[nt]);
        }
        __syncthreads();
        // SAFE POINT: all reads of stage kt's buffer completed.
        if (kt + 2 < NSTG) issue_stage(kt + 2);
    }

    // ====================== Fused epilogue ======================
    // Operand smem is dead now (barrier above passed by all warps).
    float* red = reinterpret_cast<float*>(smem_g);           // [4][128][9]
    float* w2s = reinterpret_cast<float*>(smem_g) + 4608;    // [128][9]

    // Stage this CTA's W2 chunk: rows n0..n0+127 (contiguous in W2)
    for (int i = tid; i < 128 * Csz; i += 256)
        w2s[i] = W2[(size_t)n0 * Csz + i];
    __syncthreads();

    // h = tanh(acc + b1) in place
    const int r  = lane >> 2;            // 0..7
    const int cp = (lane & 3) * 2;       // 0,2,4,6
#pragma unroll
    for (int nt = 0; nt < 4; nt++) {
        const int col = n0 + warp_n * 32 + nt * 8 + cp;
        const float b0 = bias[col];
        const float b1v = bias[col + 1];
#pragma unroll
        for (int mt = 0; mt < 4; mt++) {
            acc[mt][nt][0] = tanhf(acc[mt][nt][0] + b0);
            acc[mt][nt][1] = tanhf(acc[mt][nt][1] + b1v);
            acc[mt][nt][2] = tanhf(acc[mt][nt][2] + b0);
            acc[mt][nt][3] = tanhf(acc[mt][nt][3] + b1v);
        }
    }

    // Partial logits over this thread's 8 cols, reduced across the warp's
    // 32 cols via quad shuffles (fixed order), stored per warp_n.
#pragma unroll 1
    for (int c = 0; c < Csz; c++) {
        float w2d[4][2];
#pragma unroll
        for (int nt = 0; nt < 4; nt++) {
            const int jl = warp_n * 32 + nt * 8 + cp;   // local col in 0..127
            w2d[nt][0] = w2s[jl * Csz + c];
            w2d[nt][1] = w2s[(jl + 1) * Csz + c];
        }
#pragma unroll
        for (int mt = 0; mt < 4; mt++) {
#pragma unroll
            for (int half = 0; half < 2; half++) {
                float rs = 0.0f;
#pragma unroll
                for (int nt = 0; nt < 4; nt++)
                    rs += acc[mt][nt][half * 2 + 0] * w2d[nt][0]
                        + acc[mt][nt][half * 2 + 1] * w2d[nt][1];
                // quad reduce over lane&3 (cols) — fixed order
                rs += __shfl_xor_sync(0xffffffffu, rs, 1);
                rs += __shfl_xor_sync(0xffffffffu, rs, 2);
                if ((lane & 3) == 0) {
                    const int row = warp_m * 64 + mt * 16 + r + half * 8;
                    red[((warp_n * 128) + row) * Csz + c] = rs;
                }
            }
        }
    }
    __syncthreads();

    // Final combine (fixed order over warp_n) and write partial slice
    if (tid < 128) {
        const int row = tid;
#pragma unroll
        for (int c = 0; c < Csz; c++) {
            const float s = ((red[(0 * 128 + row) * Csz + c]  +
                              red[(1 * 128 + row) * Csz + c]) +
                             (red[(2 * 128 + row) * Csz + c]  +
                              red[(3 * 128 + row) * Csz + c]));
            PartOut[((size_t)bn * NTOK + m0 + row) * Csz + c] = s;
        }
    }
}

// ===========================================================================
// Kernel 2: sum partial logits (fixed order) + b2, softmax C=9, probs,
// per-block deterministic loss partials. One token per thread.
// ===========================================================================
__global__ __launch_bounds__(256)
void softmax_loss_kernel(const float* __restrict__ part,
                         const float* __restrict__ b2,
                         const int*   __restrict__ labels,
                         const int*   __restrict__ epoch_ptr,
                         float* __restrict__ probs_out)
{
    __shared__ float sb2[Csz];
    __shared__ float warpsum[8];
    if (threadIdx.x < Csz) sb2[threadIdx.x] = b2[threadIdx.x];
    __syncthreads();

    const int epoch = *epoch_ptr;
    const int lane  = threadIdx.x & 31;
    const int warp  = threadIdx.x >> 5;
    float lsum = 0.0f;

    for (int t = blockIdx.x * blockDim.x + threadIdx.x; t < NTOK;
         t += gridDim.x * blockDim.x) {
        float lg[Csz];
#pragma unroll
        for (int c = 0; c < Csz; c++) lg[c] = sb2[c];
#pragma unroll
        for (int p = 0; p < NBLK; p++) {
            const float* src = part + ((size_t)p * NTOK + t) * Csz;
#pragma unroll
            for (int c = 0; c < Csz; c++) lg[c] += src[c];
        }

        float m = lg[0];
#pragma unroll
        for (int c = 1; c < Csz; c++) m = fmaxf(m, lg[c]);
        float e[Csz];
        float s = 0.0f;
#pragma unroll
        for (int c = 0; c < Csz; c++) { e[c] = expf(lg[c] - m); s += e[c]; }
        const float inv_s = 1.0f / s;

        float* pd = probs_out + (size_t)t * Csz;
#pragma unroll
        for (int c = 0; c < Csz; c++) pd[c] = e[c] * inv_s;

        const int lbl = labels[t];
        if (lbl != IGNORE_LBL) {
            const float p = e[lbl] * inv_s;
            const float w = (epoch <= 2) ? 1.0f : (p > TAU_F ? 1.0f : 0.0f);
            if (w != 0.0f)
                lsum += (1.0f - powf(p, QGCE_F)) * (1.0f / QGCE_F);
        }
    }

    // Deterministic in-block reduction: fixed shfl order, then fixed warp order
#pragma unroll
    for (int o = 16; o > 0; o >>= 1)
        lsum += __shfl_xor_sync(0xffffffffu, lsum, o);
    if (lane == 0) warpsum[warp] = lsum;
    __syncthreads();
    if (threadIdx.x == 0) {
        float s = 0.0f;
#pragma unroll
        for (int w = 0; w < 8; w++) s += warpsum[w];
        g_partials[blockIdx.x] = s;
    }
}

// ===========================================================================
// Kernel 3: deterministic (fixed-order tree) final loss reduction (128)
// ===========================================================================
__global__ __launch_bounds__(128)
void finalize_loss_kernel(float* __restrict__ loss_out)
{
    __shared__ float s[128];
    const int t = threadIdx.x;
    s[t] = g_partials[t];
    __syncthreads();
#pragma unroll
    for (int o = 64; o > 0; o >>= 1) {
        if (t < o) s[t] += s[t + o];
        __syncthreads();
    }
    if (t == 0) *loss_out = s[0];
}

// ===========================================================================
// Launch. Inputs: hidden, W1, b1, W2, b2, labels, epoch.
// Output: probs [B*S*C] fp32, then loss [1] fp32.
// ===========================================================================
extern "C" void kernel_launch(void* const* d_in, const int* in_sizes, int n_in,
                              void* d_out, int out_size)
{
    const float* hidden = (const float*)d_in[0];
    const float* W1     = (const float*)d_in[1];
    const float* b1     = (const float*)d_in[2];
    const float* W2     = (const float*)d_in[3];
    const float* b2     = (const float*)d_in[4];
    const int*   labels = (const int*)  d_in[5];
    const int*   epoch  = (const int*)  d_in[6];

    float* out = (float*)d_out;
    const int PROBS_N = NTOK * Csz;   // 294912

    float* probs_dst = out;
    float* loss_dst  = nullptr;
    if (out_size >= PROBS_N + 1) {
        loss_dst = out + PROBS_N;
    } else if (out_size < PROBS_N) {
        void* sink = nullptr;
        cudaGetSymbolAddress(&sink, g_probs_sink);
        probs_dst = (float*)sink;
        if (out_size >= 1) loss_dst = out;
    }

    __nv_bfloat16 *a_hi = nullptr, *a_lo = nullptr, *w1t_hi = nullptr, *w1t_lo = nullptr;
    float* part = nullptr;
    cudaGetSymbolAddress((void**)&a_hi, g_A_hi);
    cudaGetSymbolAddress((void**)&a_lo, g_A_lo);
    cudaGetSymbolAddress((void**)&w1t_hi, g_W1T_hi);
    cudaGetSymbolAddress((void**)&w1t_lo, g_W1T_lo);
    cudaGetSymbolAddress((void**)&part, g_part);

    // 0) split A and W1 to bf16 hi/lo
    const int n4 = NTOK * Esz / 4;    // 6291456 float4s
    split_a_kernel<<<6144, 256>>>((const float4*)hidden,
                                  (uint2*)a_hi, (uint2*)a_lo, n4);
    split_w1_kernel<<<dim3(Hsz / 32, Esz / 32), dim3(32, 8)>>>(W1, w1t_hi, w1t_lo);

    // 1) fused GEMM1 + tanh + partial GEMM2 (h never hits global memory)
    cudaFuncSetAttribute(gemm1_mma_kernel,
                         cudaFuncAttributeMaxDynamicSharedMemorySize, GEMM_SMEM);
    dim3 g1(Hsz / 128, NTOK / 128);   // (6, 256)
    gemm1_mma_kernel<<<g1, 256, GEMM_SMEM>>>(a_hi, a_lo, w1t_hi, w1t_lo,
                                             b1, W2, part);

    // 2) combine partials + softmax + probs + loss partials
    softmax_loss_kernel<<<LOSS_BLOCKS, 256>>>(part, b2, labels, epoch, probs_dst);

    // 3) deterministic loss finalize
    if (loss_dst != nullptr)
        finalize_loss_kernel<<<1, 128>>>(loss_dst);
}